// round 12
// baseline (speedup 1.0000x reference)
#include <cuda_runtime.h>
#include <cuda_fp16.h>
#include <cstdint>

// Problem constants
#define Bb 4
#define Ss 2048
#define Dd 1024
#define Hh 16
#define DHd 64
#define MM (Bb * Ss)          // 8192
#define N1 (3 * Dd)           // 3072

#define LO_SCALE 2048.0f
#define INV_LO   (1.0f / 2048.0f)

// ---------------- global scratch (fp16 hi/lo planes; lo scaled by 2048) -----
__device__ __half g_xhi[(size_t)MM * Dd];
__device__ __half g_xlo[(size_t)MM * Dd];
__device__ __half g_w1hi[(size_t)N1 * Dd];    // [n][k]
__device__ __half g_w1lo[(size_t)N1 * Dd];
__device__ __half g_w2hi[(size_t)Dd * Dd];    // [n][k]
__device__ __half g_qkvhi[(size_t)MM * N1];
__device__ __half g_qkvlo[(size_t)MM * N1];   // lo valid for Q,K cols (scaled)
__device__ __half g_ahi[(size_t)MM * Dd];

// ---------------- helpers ----------------
__device__ __forceinline__ uint32_t s2u(const void* p) {
    uint32_t a;
    asm("{ .reg .u64 t; cvta.to.shared.u64 t, %1; cvt.u32.u64 %0, t; }" : "=r"(a) : "l"(p));
    return a;
}
__device__ __forceinline__ void cp16(uint32_t saddr, const void* gaddr) {
    asm volatile("cp.async.cg.shared.global [%0], [%1], 16;" :: "r"(saddr), "l"(gaddr));
}
#define CP_COMMIT() asm volatile("cp.async.commit_group;" ::: "memory")
#define CP_WAIT0()  asm volatile("cp.async.wait_group 0;" ::: "memory")

__device__ __forceinline__ void ldmx4(uint32_t* r, uint32_t addr) {
    asm volatile("ldmatrix.sync.aligned.m8n8.x4.shared.b16 {%0,%1,%2,%3}, [%4];"
        : "=r"(r[0]), "=r"(r[1]), "=r"(r[2]), "=r"(r[3]) : "r"(addr));
}
__device__ __forceinline__ void ldmx4t(uint32_t* r, uint32_t addr) {
    asm volatile("ldmatrix.sync.aligned.m8n8.x4.trans.shared.b16 {%0,%1,%2,%3}, [%4];"
        : "=r"(r[0]), "=r"(r[1]), "=r"(r[2]), "=r"(r[3]) : "r"(addr));
}
// fp32-accumulator MMA
__device__ __forceinline__ void mma_f16(float* c, const uint32_t* a, const uint32_t* b) {
    asm volatile("mma.sync.aligned.m16n8k16.row.col.f32.f16.f16.f32 "
        "{%0,%1,%2,%3}, {%4,%5,%6,%7}, {%8,%9}, {%0,%1,%2,%3};"
        : "+f"(c[0]), "+f"(c[1]), "+f"(c[2]), "+f"(c[3])
        : "r"(a[0]), "r"(a[1]), "r"(a[2]), "r"(a[3]), "r"(b[0]), "r"(b[1]));
}
// fp16-accumulator MMA (correction passes; hypothesized 2x rate)
__device__ __forceinline__ void mma_f16h(uint32_t* c, const uint32_t* a, const uint32_t* b) {
    asm volatile("mma.sync.aligned.m16n8k16.row.col.f16.f16.f16.f16 "
        "{%0,%1}, {%2,%3,%4,%5}, {%6,%7}, {%0,%1};"
        : "+r"(c[0]), "+r"(c[1])
        : "r"(a[0]), "r"(a[1]), "r"(a[2]), "r"(a[3]), "r"(b[0]), "r"(b[1]));
}
__device__ __forceinline__ void unpack_h2(uint32_t v, float& f0, float& f1) {
    __half2 h = *reinterpret_cast<__half2*>(&v);
    float2 f = __half22float2(h);
    f0 = f.x; f1 = f.y;
}
// fp32 pair -> fp16 hi pair + SCALED fp16 lo pair (lo = rn((f-hi)*2048))
__device__ __forceinline__ void cvt_packh(float f0, float f1, uint32_t& hi, uint32_t& lo) {
    __half h0 = __float2half_rn(f0);
    __half h1 = __float2half_rn(f1);
    __half l0 = __float2half_rn((f0 - __half2float(h0)) * LO_SCALE);
    __half l1 = __float2half_rn((f1 - __half2float(h1)) * LO_SCALE);
    hi = ((uint32_t)__half_as_ushort(h1) << 16) | (uint32_t)__half_as_ushort(h0);
    lo = ((uint32_t)__half_as_ushort(l1) << 16) | (uint32_t)__half_as_ushort(l0);
}
__device__ __forceinline__ uint32_t pack_h(float f0, float f1) {
    __half h0 = __float2half_rn(f0);
    __half h1 = __float2half_rn(f1);
    return ((uint32_t)__half_as_ushort(h1) << 16) | (uint32_t)__half_as_ushort(h0);
}

// ---------------- pre-convert kernels ----------------
__global__ void __launch_bounds__(256) split_f32(
    const float* __restrict__ src, __half* __restrict__ hi,
    __half* __restrict__ lo, int n2)
{
    int i = blockIdx.x * 256 + threadIdx.x;
    if (i >= n2) return;
    float2 v = *(const float2*)(src + 2 * i);
    uint32_t h, l;
    cvt_packh(v.x, v.y, h, l);
    ((uint32_t*)hi)[i] = h;
    ((uint32_t*)lo)[i] = l;
}

// W[K][N] fp32 -> Wt hi(/scaled lo) [N][K] fp16
__global__ void __launch_bounds__(256) transpose_split(
    const float* __restrict__ W, __half* __restrict__ Whi,
    __half* __restrict__ Wlo, int K, int N, int write_lo)
{
    __shared__ float sm[64][33];
    const int tid = threadIdx.x;
    const int n0 = blockIdx.x * 32;
    const int k0 = blockIdx.y * 64;
#pragma unroll
    for (int p = 0; p < 8; p++) {
        const int k = p * 8 + (tid >> 5);
        const int n = tid & 31;
        sm[k][n] = W[(size_t)(k0 + k) * N + n0 + n];
    }
    __syncthreads();
#pragma unroll
    for (int p = 0; p < 4; p++) {
        const int n = p * 8 + (tid >> 5);
        const int kp = tid & 31;
        uint32_t h, l;
        cvt_packh(sm[2 * kp][n], sm[2 * kp + 1][n], h, l);
        const size_t idx = ((size_t)(n0 + n) * K + k0) / 2 + kp;
        ((uint32_t*)Whi)[idx] = h;
        if (write_lo) ((uint32_t*)Wlo)[idx] = l;
    }
}

// ---------------------------------------------------------------------------
// GEMM from fp16 planes. C = A @ B^T(+bias), A [M][K], B [N][K].
// 128x128 tile, BK=32, cp.async double-buffered, 8 warps (2m x 4n).
// Main pass ah·bh: fp32 accum. Correction passes (ah·bl', al'·bh) run with
// fp16 accumulators on 2048-scaled lo planes, drained into fp32 acc per step.
// ---------------------------------------------------------------------------
#define GST 80
#define GTILE (128 * GST)
#define GSTAGE (4 * GTILE)
#define GEMM_SMEM (2 * GSTAGE)

template<int EPI>
__global__ void __launch_bounds__(256, 2) gemm_hf(
    const __half* __restrict__ Ahi, const __half* __restrict__ Alo,
    const __half* __restrict__ Bhi, const __half* __restrict__ Blo,
    const float* __restrict__ bias, float* __restrict__ Cf,
    __half* __restrict__ Chi, __half* __restrict__ Clo,
    int M, int N, int K, int n3lim, int alo_lo, int alo_hi,
    int wlo_lo, int wlo_hi)
{
    extern __shared__ char smem[];
    const int tid = threadIdx.x;
    const int lane = tid & 31;
    const int warp = tid >> 5;
    const int wm = warp >> 2;
    const int wn = warp & 3;
    const int row0 = blockIdx.y * 128;
    const int col0 = blockIdx.x * 128;
    const bool use3 = (col0 < n3lim);
    const bool ualo = (col0 >= alo_lo) && (col0 < alo_hi);

    const int lrow = tid >> 1;
    const int lq = (tid & 1) * 2;

    auto issue = [&](int kc, int s) {
        char* stg = smem + s * GSTAGE;
        const uint32_t sA = s2u(stg) + (uint32_t)lrow * GST + lq * 16;
        const size_t gOffA = (size_t)(row0 + lrow) * K + kc * 32 + lq * 8;
        cp16(sA, Ahi + gOffA);
        cp16(sA + 16, Ahi + gOffA + 8);
        if (ualo) {
            cp16(sA + GTILE, Alo + gOffA);
            cp16(sA + GTILE + 16, Alo + gOffA + 8);
        }
        const size_t gOffB = (size_t)(col0 + lrow) * K + kc * 32 + lq * 8;
        cp16(sA + 2 * GTILE, Bhi + gOffB);
        cp16(sA + 2 * GTILE + 16, Bhi + gOffB + 8);
        if (use3) {
            cp16(sA + 3 * GTILE, Blo + gOffB);
            cp16(sA + 3 * GTILE + 16, Blo + gOffB + 8);
        }
    };

    float acc[4][4][4];
#pragma unroll
    for (int i = 0; i < 4; i++)
#pragma unroll
        for (int j = 0; j < 4; j++)
#pragma unroll
            for (int e = 0; e < 4; e++) acc[i][j][e] = 0.f;

    const uint32_t fragoff = (uint32_t)(lane & 15) * GST + (uint32_t)(lane >> 4) * 16;

    issue(0, 0);
    CP_COMMIT();

    const int nch = K / 32;
    for (int kc = 0; kc < nch; kc++) {
        const int s = kc & 1;
        CP_WAIT0();
        __syncthreads();
        if (kc + 1 < nch) {
            issue(kc + 1, s ^ 1);
            CP_COMMIT();
        }
        char* stg = smem + s * GSTAGE;
        const uint32_t uAhi = s2u(stg);
        const uint32_t uAlo = uAhi + GTILE;
        const uint32_t uBhi = uAhi + 2 * GTILE;
        const uint32_t uBlo = uAhi + 3 * GTILE;

#pragma unroll
        for (int ks = 0; ks < 2; ks++) {
            const uint32_t kb = (uint32_t)ks * 32;
            uint32_t bh[4][2], bl[4][2];
#pragma unroll
            for (int ntp = 0; ntp < 2; ntp++) {
                const uint32_t boff = (uint32_t)(wn * 32 + ntp * 16) * GST + kb + fragoff;
                uint32_t m[4];
                ldmx4(m, uBhi + boff);
                bh[ntp * 2 + 0][0] = m[0]; bh[ntp * 2 + 1][0] = m[1];
                bh[ntp * 2 + 0][1] = m[2]; bh[ntp * 2 + 1][1] = m[3];
                if (use3) {
                    ldmx4(m, uBlo + boff);
                    bl[ntp * 2 + 0][0] = m[0]; bl[ntp * 2 + 1][0] = m[1];
                    bl[ntp * 2 + 0][1] = m[2]; bl[ntp * 2 + 1][1] = m[3];
                }
            }
            uint32_t ah[4][4];
#pragma unroll
            for (int mt = 0; mt < 4; mt++) {
                const uint32_t aoff = (uint32_t)(wm * 64 + mt * 16) * GST + kb + fragoff;
                ldmx4(ah[mt], uAhi + aoff);
            }
            // PASS 1: ah·bh (fp32 accum)
#pragma unroll
            for (int mt = 0; mt < 4; mt++)
#pragma unroll
                for (int nt = 0; nt < 4; nt++)
                    mma_f16(acc[mt][nt], ah[mt], bh[nt]);

            // Correction passes (fp16 accum, scaled lo), per mt-pair
            if (use3 || ualo) {
#pragma unroll
                for (int mtp = 0; mtp < 2; mtp++) {
                    uint32_t cor[2][4][2];
#pragma unroll
                    for (int m2 = 0; m2 < 2; m2++)
#pragma unroll
                        for (int nt = 0; nt < 4; nt++) {
                            cor[m2][nt][0] = 0u; cor[m2][nt][1] = 0u;
                        }
                    if (use3) {
#pragma unroll
                        for (int m2 = 0; m2 < 2; m2++)
#pragma unroll
                            for (int nt = 0; nt < 4; nt++)
                                mma_f16h(cor[m2][nt], ah[mtp * 2 + m2], bl[nt]);
                    }
                    if (ualo) {
#pragma unroll
                        for (int m2 = 0; m2 < 2; m2++) {
                            const uint32_t aoff =
                                (uint32_t)(wm * 64 + (mtp * 2 + m2) * 16) * GST + kb + fragoff;
                            uint32_t al[4];
                            ldmx4(al, uAlo + aoff);
#pragma unroll
                            for (int nt = 0; nt < 4; nt++)
                                mma_f16h(cor[m2][nt], al, bh[nt]);
                        }
                    }
                    // drain into fp32 acc with 1/2048
#pragma unroll
                    for (int m2 = 0; m2 < 2; m2++)
#pragma unroll
                        for (int nt = 0; nt < 4; nt++) {
                            float f0, f1, f2, f3;
                            unpack_h2(cor[m2][nt][0], f0, f1);
                            unpack_h2(cor[m2][nt][1], f2, f3);
                            float* a = acc[mtp * 2 + m2][nt];
                            a[0] += f0 * INV_LO;
                            a[1] += f1 * INV_LO;
                            a[2] += f2 * INV_LO;
                            a[3] += f3 * INV_LO;
                        }
                }
            }
        }
    }

    // epilogue
    const bool wlo = (col0 >= wlo_lo) && (col0 < wlo_hi);
#pragma unroll
    for (int mt = 0; mt < 4; mt++) {
        const int r = row0 + wm * 64 + mt * 16 + (lane >> 2);
#pragma unroll
        for (int nt = 0; nt < 4; nt++) {
            const int c = col0 + wn * 32 + nt * 8 + (lane & 3) * 2;
            const float bx = bias[c];
            const float by = bias[c + 1];
            const float f0 = acc[mt][nt][0] + bx;
            const float f1 = acc[mt][nt][1] + by;
            const float f2 = acc[mt][nt][2] + bx;
            const float f3 = acc[mt][nt][3] + by;
            if (EPI == 0) {
                *(float2*)(Cf + (size_t)r * N + c) = make_float2(f0, f1);
                *(float2*)(Cf + (size_t)(r + 8) * N + c) = make_float2(f2, f3);
            } else {
                uint32_t h0, l0, h1, l1;
                cvt_packh(f0, f1, h0, l0);
                cvt_packh(f2, f3, h1, l1);
                const size_t i0 = ((size_t)r * N + c) / 2;
                const size_t i1 = ((size_t)(r + 8) * N + c) / 2;
                ((uint32_t*)Chi)[i0] = h0;
                ((uint32_t*)Chi)[i1] = h1;
                if (wlo) {
                    ((uint32_t*)Clo)[i0] = l0;
                    ((uint32_t*)Clo)[i1] = l1;
                }
            }
        }
    }
}

// ---------------------------------------------------------------------------
// Flash attention from fp16 qkv planes (lo planes scaled by 2048).
// QK: pass1 qh·Khi fp32 accum; passes 2,3 (qh·Klo', ql'·Khi) fp16 accum,
// drained /2048 before softmax. PV: 1-MMA fp32. Output: hi plane only.
// ---------------------------------------------------------------------------
#define AST 144
#define ATL (64 * AST)
#define ASTG (3 * ATL)              // Khi,Klo,Vhi = 27648
#define ATTN_SMEM (ASTG + 2 * 128 * AST)   // 64512 (Q hi+lo staging overlaps stage1)

__global__ void __launch_bounds__(256) flash2(
    const __half* __restrict__ qhi, const __half* __restrict__ qlo,
    __half* __restrict__ ohi)
{
    extern __shared__ char smem[];
    const int tid = threadIdx.x;
    const int lane = tid & 31;
    const int warp = tid >> 5;
    const int qt = blockIdx.x;
    const int bh = blockIdx.y;
    const int b = bh >> 4;
    const int h = bh & 15;

    const uint32_t sb = s2u(smem);
    const uint32_t fragoff = (uint32_t)(lane & 15) * AST + (uint32_t)(lane >> 4) * 16;
    const size_t headoff = (size_t)h * DHd;

    const int krow = tid >> 2;
    const int kcc = (tid & 3) * 2;
    auto issueKV = [&](int kb, int s) {
        const uint32_t sB = sb + s * ASTG + (uint32_t)krow * AST + kcc * 16;
        const size_t g = ((size_t)b * Ss + kb * 64 + krow) * N1 + headoff + kcc * 8;
        cp16(sB,                 qhi + g + Dd);       // K hi
        cp16(sB + 16,            qhi + g + Dd + 8);
        cp16(sB + ATL,           qlo + g + Dd);       // K lo (scaled)
        cp16(sB + ATL + 16,      qlo + g + Dd + 8);
        cp16(sB + 2 * ATL,       qhi + g + 2 * Dd);   // V hi
        cp16(sB + 2 * ATL + 16,  qhi + g + 2 * Dd + 8);
    };

    // preload: K/V block0 -> stage0; Q hi+lo -> region above stage0 (overlaps
    // stage1; safe: Q is consumed into registers before stage1 is written)
    issueKV(0, 0);
    CP_COMMIT();
    {
        const int qrow = tid >> 1;
        const int q4 = (tid & 1) * 4;
        const uint32_t sQh = sb + ASTG + (uint32_t)qrow * AST + q4 * 16;
        const uint32_t sQl = sQh + 128 * AST;
        const size_t g = ((size_t)b * Ss + qt * 128 + qrow) * N1 + headoff + q4 * 8;
#pragma unroll
        for (int i = 0; i < 4; i++) {
            cp16(sQh + i * 16, qhi + g + i * 8);
            cp16(sQl + i * 16, qlo + g + i * 8);
        }
    }
    CP_COMMIT();
    CP_WAIT0();
    __syncthreads();

    // Q fragments (extracted before stage1 is ever written)
    uint32_t qh[4][4], ql[4][4];
    {
        const uint32_t uQh = sb + ASTG;
        const uint32_t uQl = uQh + 128 * AST;
#pragma unroll
        for (int j = 0; j < 4; j++) {
            const uint32_t aoff = (uint32_t)(warp * 16) * AST + j * 32 + fragoff;
            ldmx4(qh[j], uQh + aoff);
            ldmx4(ql[j], uQl + aoff);
        }
    }

    float o[8][4];
    float m0 = -1e30f, m1 = -1e30f, l0 = 0.f, l1 = 0.f;
#pragma unroll
    for (int i = 0; i < 8; i++)
#pragma unroll
        for (int e = 0; e < 4; e++) o[i][e] = 0.f;

    for (int kb = 0; kb < Ss / 64; kb++) {
        const int s = kb & 1;
        if (kb > 0) CP_WAIT0();
        __syncthreads();
        if (kb + 1 < Ss / 64) {
            issueKV(kb + 1, s ^ 1);
            CP_COMMIT();
        }
        const uint32_t uKhi = sb + s * ASTG;
        const uint32_t uKlo = uKhi + ATL;
        const uint32_t uVhi = uKhi + 2 * ATL;

        // ---- S = Q K^T: main fp32, corrections fp16-acc ----
        float sc[8][4];
        uint32_t cor[8][2];
#pragma unroll
        for (int i = 0; i < 8; i++) {
#pragma unroll
            for (int e = 0; e < 4; e++) sc[i][e] = 0.f;
            cor[i][0] = 0u; cor[i][1] = 0u;
        }

#pragma unroll
        for (int j = 0; j < 4; j++) {
            // pass 1: qh · Khi (fp32 acc)
#pragma unroll
            for (int g = 0; g < 4; g++) {
                const uint32_t boff = (uint32_t)(g * 16) * AST + j * 32 + fragoff;
                uint32_t mh[4];
                ldmx4(mh, uKhi + boff);
                uint32_t b0[2] = {mh[0], mh[2]}, b1[2] = {mh[1], mh[3]};
                mma_f16(sc[2 * g + 0], qh[j], b0);
                mma_f16(sc[2 * g + 1], qh[j], b1);
            }
            // pass 2: qh · Klo' (fp16 acc)
#pragma unroll
            for (int g = 0; g < 4; g++) {
                const uint32_t boff = (uint32_t)(g * 16) * AST + j * 32 + fragoff;
                uint32_t ml[4];
                ldmx4(ml, uKlo + boff);
                uint32_t b0[2] = {ml[0], ml[2]}, b1[2] = {ml[1], ml[3]};
                mma_f16h(cor[2 * g + 0], qh[j], b0);
                mma_f16h(cor[2 * g + 1], qh[j], b1);
            }
            // pass 3: ql' · Khi (fp16 acc, reload hi frags)
#pragma unroll
            for (int g = 0; g < 4; g++) {
                const uint32_t boff = (uint32_t)(g * 16) * AST + j * 32 + fragoff;
                uint32_t mh[4];
                ldmx4(mh, uKhi + boff);
                uint32_t b0[2] = {mh[0], mh[2]}, b1[2] = {mh[1], mh[3]};
                mma_f16h(cor[2 * g + 0], ql[j], b0);
                mma_f16h(cor[2 * g + 1], ql[j], b1);
            }
        }
        // drain corrections
#pragma unroll
        for (int i = 0; i < 8; i++) {
            float f0, f1, f2, f3;
            unpack_h2(cor[i][0], f0, f1);
            unpack_h2(cor[i][1], f2, f3);
            sc[i][0] += f0 * INV_LO;
            sc[i][1] += f1 * INV_LO;
            sc[i][2] += f2 * INV_LO;
            sc[i][3] += f3 * INV_LO;
        }

        // ---- online softmax ----
        float mx0 = -1e30f, mx1 = -1e30f;
#pragma unroll
        for (int i = 0; i < 8; i++) {
            mx0 = fmaxf(mx0, fmaxf(sc[i][0], sc[i][1]));
            mx1 = fmaxf(mx1, fmaxf(sc[i][2], sc[i][3]));
        }
        mx0 = fmaxf(mx0, __shfl_xor_sync(0xffffffffu, mx0, 1));
        mx0 = fmaxf(mx0, __shfl_xor_sync(0xffffffffu, mx0, 2));
        mx1 = fmaxf(mx1, __shfl_xor_sync(0xffffffffu, mx1, 1));
        mx1 = fmaxf(mx1, __shfl_xor_sync(0xffffffffu, mx1, 2));
        const float mn0 = fmaxf(m0, mx0);
        const float mn1 = fmaxf(m1, mx1);
        const float c0 = __expf(m0 - mn0);
        const float c1 = __expf(m1 - mn1);
        float rs0 = 0.f, rs1 = 0.f;
#pragma unroll
        for (int i = 0; i < 8; i++) {
            sc[i][0] = __expf(sc[i][0] - mn0);
            sc[i][1] = __expf(sc[i][1] - mn0);
            sc[i][2] = __expf(sc[i][2] - mn1);
            sc[i][3] = __expf(sc[i][3] - mn1);
            rs0 += sc[i][0] + sc[i][1];
            rs1 += sc[i][2] + sc[i][3];
        }
        rs0 += __shfl_xor_sync(0xffffffffu, rs0, 1);
        rs0 += __shfl_xor_sync(0xffffffffu, rs0, 2);
        rs1 += __shfl_xor_sync(0xffffffffu, rs1, 1);
        rs1 += __shfl_xor_sync(0xffffffffu, rs1, 2);
        l0 = l0 * c0 + rs0;
        l1 = l1 * c1 + rs1;
        m0 = mn0;
        m1 = mn1;
#pragma unroll
        for (int i = 0; i < 8; i++) {
            o[i][0] *= c0; o[i][1] *= c0;
            o[i][2] *= c1; o[i][3] *= c1;
        }

        // ---- repack P hi only (C-frag -> A-frag) ----
        uint32_t ph[4][4];
#pragma unroll
        for (int j = 0; j < 4; j++) {
            ph[j][0] = pack_h(sc[2 * j][0],     sc[2 * j][1]);
            ph[j][1] = pack_h(sc[2 * j][2],     sc[2 * j][3]);
            ph[j][2] = pack_h(sc[2 * j + 1][0], sc[2 * j + 1][1]);
            ph[j][3] = pack_h(sc[2 * j + 1][2], sc[2 * j + 1][3]);
        }

        // ---- O += P V (1-MMA fp32 acc, acc distance 8 across g) ----
#pragma unroll
        for (int j = 0; j < 4; j++) {
#pragma unroll
            for (int g = 0; g < 4; g++) {
                const uint32_t voff = (uint32_t)(j * 16) * AST + g * 32 + fragoff;
                uint32_t mh[4];
                ldmx4t(mh, uVhi + voff);
                uint32_t b0[2] = {mh[0], mh[1]}, b1[2] = {mh[2], mh[3]};
                mma_f16(o[2 * g + 0], ph[j], b0);
                mma_f16(o[2 * g + 1], ph[j], b1);
            }
        }
    }

    // ---- epilogue: write hi plane only ----
    const float inv0 = 1.f / l0;
    const float inv1 = 1.f / l1;
    const int r0 = qt * 128 + warp * 16 + (lane >> 2);
    const size_t base0 = ((size_t)b * Ss + r0) * Dd + headoff + (lane & 3) * 2;
    const size_t base1 = base0 + (size_t)8 * Dd;
#pragma unroll
    for (int nt = 0; nt < 8; nt++) {
        ((uint32_t*)ohi)[(base0 + nt * 8) / 2] = pack_h(o[nt][0] * inv0, o[nt][1] * inv0);
        ((uint32_t*)ohi)[(base1 + nt * 8) / 2] = pack_h(o[nt][2] * inv1, o[nt][3] * inv1);
    }
}

// ---------------------------------------------------------------------------
extern "C" void kernel_launch(void* const* d_in, const int* in_sizes, int n_in,
                              void* d_out, int out_size)
{
    (void)in_sizes; (void)n_in; (void)out_size;
    const float* x  = (const float*)d_in[0];
    const float* w1 = (const float*)d_in[1];
    const float* b1 = (const float*)d_in[2];
    const float* w2 = (const float*)d_in[3];
    const float* b2 = (const float*)d_in[4];
    float* out = (float*)d_out;

    __half *xhi, *xlo, *w1hi, *w1lo, *w2hi, *qhi, *qlo, *ahi;
    cudaGetSymbolAddress((void**)&xhi, g_xhi);
    cudaGetSymbolAddress((void**)&xlo, g_xlo);
    cudaGetSymbolAddress((void**)&w1hi, g_w1hi);
    cudaGetSymbolAddress((void**)&w1lo, g_w1lo);
    cudaGetSymbolAddress((void**)&w2hi, g_w2hi);
    cudaGetSymbolAddress((void**)&qhi, g_qkvhi);
    cudaGetSymbolAddress((void**)&qlo, g_qkvlo);
    cudaGetSymbolAddress((void**)&ahi, g_ahi);

    cudaFuncSetAttribute(gemm_hf<0>, cudaFuncAttributeMaxDynamicSharedMemorySize, GEMM_SMEM);
    cudaFuncSetAttribute(gemm_hf<1>, cudaFuncAttributeMaxDynamicSharedMemorySize, GEMM_SMEM);
    cudaFuncSetAttribute(flash2, cudaFuncAttributeMaxDynamicSharedMemorySize, ATTN_SMEM);

    // pre-convert (lo planes scaled by 2048)
    split_f32<<<(MM * Dd / 2 + 255) / 256, 256>>>(x, xhi, xlo, MM * Dd / 2);
    transpose_split<<<dim3(N1 / 32, Dd / 64), 256>>>(w1, w1hi, w1lo, Dd, N1, 1);
    transpose_split<<<dim3(Dd / 32, Dd / 64), 256>>>(w2, w2hi, nullptr, Dd, Dd, 0);

    // 1) QKV projection -> fp16 planes:
    //    Q,K cols [0,2048):  main fp32 + 2 fp16-acc correction passes, hi+lo out
    //    V cols [2048,3072): 1-MMA, hi out
    gemm_hf<1><<<dim3(N1 / 128, MM / 128), 256, GEMM_SMEM>>>(
        xhi, xlo, w1hi, w1lo, b1, nullptr, qhi, qlo, MM, N1, Dd,
        /*n3lim=*/2 * Dd, /*alo=*/0, 2 * Dd, /*wlo=*/0, 2 * Dd);
    // 2) attention (QK main fp32 + fp16-acc corrections, PV 1-MMA) -> a hi plane
    flash2<<<dim3(Ss / 128, Bb * Hh), 256, ATTN_SMEM>>>(qhi, qlo, ahi);
    // 3) output projection (1-MMA pure fp16, fp32 acc) -> fp32 out
    gemm_hf<0><<<dim3(Dd / 128, MM / 128), 256, GEMM_SMEM>>>(
        ahi, nullptr, w2hi, nullptr, b2, out, nullptr, nullptr, MM, Dd, Dd,
        /*n3lim=*/0, /*alo=*/0, 0, /*wlo=*/0, 0);
}

// round 13
// speedup vs baseline: 1.1405x; 1.1405x over previous
#include <cuda_runtime.h>
#include <cuda_fp16.h>
#include <cstdint>

// Problem constants
#define Bb 4
#define Ss 2048
#define Dd 1024
#define Hh 16
#define DHd 64
#define MM (Bb * Ss)          // 8192
#define N1 (3 * Dd)           // 3072

// ---------------- global scratch (fp16 hi/lo planes) ----------------
__device__ __half g_xhi[(size_t)MM * Dd];
__device__ __half g_xlo[(size_t)MM * Dd];
__device__ __half g_w1hi[(size_t)N1 * Dd];    // [n][k]
__device__ __half g_w1lo[(size_t)N1 * Dd];
__device__ __half g_w2hi[(size_t)Dd * Dd];    // [n][k]
__device__ __half g_qkvhi[(size_t)MM * N1];
__device__ __half g_qkvlo[(size_t)MM * N1];   // lo valid for Q,K cols
__device__ __half g_ahi[(size_t)MM * Dd];

// ---------------- helpers ----------------
__device__ __forceinline__ uint32_t s2u(const void* p) {
    uint32_t a;
    asm("{ .reg .u64 t; cvta.to.shared.u64 t, %1; cvt.u32.u64 %0, t; }" : "=r"(a) : "l"(p));
    return a;
}
__device__ __forceinline__ void cp16(uint32_t saddr, const void* gaddr) {
    asm volatile("cp.async.cg.shared.global [%0], [%1], 16;" :: "r"(saddr), "l"(gaddr));
}
#define CP_COMMIT() asm volatile("cp.async.commit_group;" ::: "memory")
#define CP_WAIT0()  asm volatile("cp.async.wait_group 0;" ::: "memory")

__device__ __forceinline__ void ldmx4(uint32_t* r, uint32_t addr) {
    asm volatile("ldmatrix.sync.aligned.m8n8.x4.shared.b16 {%0,%1,%2,%3}, [%4];"
        : "=r"(r[0]), "=r"(r[1]), "=r"(r[2]), "=r"(r[3]) : "r"(addr));
}
__device__ __forceinline__ void ldmx4t(uint32_t* r, uint32_t addr) {
    asm volatile("ldmatrix.sync.aligned.m8n8.x4.trans.shared.b16 {%0,%1,%2,%3}, [%4];"
        : "=r"(r[0]), "=r"(r[1]), "=r"(r[2]), "=r"(r[3]) : "r"(addr));
}
__device__ __forceinline__ void mma_f16(float* c, const uint32_t* a, const uint32_t* b) {
    asm volatile("mma.sync.aligned.m16n8k16.row.col.f32.f16.f16.f32 "
        "{%0,%1,%2,%3}, {%4,%5,%6,%7}, {%8,%9}, {%0,%1,%2,%3};"
        : "+f"(c[0]), "+f"(c[1]), "+f"(c[2]), "+f"(c[3])
        : "r"(a[0]), "r"(a[1]), "r"(a[2]), "r"(a[3]), "r"(b[0]), "r"(b[1]));
}
// fp32 pair -> packed fp16 hi pair + fp16 lo pair (hi = rn(f), lo = rn(f - hi))
__device__ __forceinline__ void cvt_packh(float f0, float f1, uint32_t& hi, uint32_t& lo) {
    __half h0 = __float2half_rn(f0);
    __half h1 = __float2half_rn(f1);
    __half l0 = __float2half_rn(f0 - __half2float(h0));
    __half l1 = __float2half_rn(f1 - __half2float(h1));
    hi = ((uint32_t)__half_as_ushort(h1) << 16) | (uint32_t)__half_as_ushort(h0);
    lo = ((uint32_t)__half_as_ushort(l1) << 16) | (uint32_t)__half_as_ushort(l0);
}
__device__ __forceinline__ uint32_t pack_h(float f0, float f1) {
    __half h0 = __float2half_rn(f0);
    __half h1 = __float2half_rn(f1);
    return ((uint32_t)__half_as_ushort(h1) << 16) | (uint32_t)__half_as_ushort(h0);
}

// ---------------- pre-convert kernels ----------------
__global__ void __launch_bounds__(256) split_f32(
    const float* __restrict__ src, __half* __restrict__ hi,
    __half* __restrict__ lo, int n2)
{
    int i = blockIdx.x * 256 + threadIdx.x;
    if (i >= n2) return;
    float2 v = *(const float2*)(src + 2 * i);
    uint32_t h, l;
    cvt_packh(v.x, v.y, h, l);
    ((uint32_t*)hi)[i] = h;
    ((uint32_t*)lo)[i] = l;
}

// W[K][N] fp32 -> Wt hi(/lo) [N][K] fp16
__global__ void __launch_bounds__(256) transpose_split(
    const float* __restrict__ W, __half* __restrict__ Whi,
    __half* __restrict__ Wlo, int K, int N, int write_lo)
{
    __shared__ float sm[64][33];
    const int tid = threadIdx.x;
    const int n0 = blockIdx.x * 32;
    const int k0 = blockIdx.y * 64;
#pragma unroll
    for (int p = 0; p < 8; p++) {
        const int k = p * 8 + (tid >> 5);
        const int n = tid & 31;
        sm[k][n] = W[(size_t)(k0 + k) * N + n0 + n];
    }
    __syncthreads();
#pragma unroll
    for (int p = 0; p < 4; p++) {
        const int n = p * 8 + (tid >> 5);
        const int kp = tid & 31;
        uint32_t h, l;
        cvt_packh(sm[2 * kp][n], sm[2 * kp + 1][n], h, l);
        const size_t idx = ((size_t)(n0 + n) * K + k0) / 2 + kp;
        ((uint32_t*)Whi)[idx] = h;
        if (write_lo) ((uint32_t*)Wlo)[idx] = l;
    }
}

// ---------------------------------------------------------------------------
// GEMM from fp16 planes. C = A @ B^T(+bias), A [M][K], B [N][K].
// CTA tile 64x128 (small-M for occupancy: 3 CTAs/SM = 24 warps), BK=32,
// cp.async double-buffered, 8 warps (2m x 4n), warp tile 32x32.
// Passes: ah·bh always; ah·bl when col0 < n3lim; al·bh in [alo_lo, alo_hi).
// EPI: 0 -> fp32 C, 1 -> fp16 hi plane (+lo when col0 in [wlo_lo, wlo_hi)).
// ---------------------------------------------------------------------------
#define GST 80
#define GTA (64 * GST)              // 5120  (A plane: 64 rows)
#define GTB (128 * GST)             // 10240 (B plane: 128 rows)
#define GSTAGE (2 * GTA + 2 * GTB)  // 30720
#define GEMM_SMEM (2 * GSTAGE)      // 61440 -> 3 CTAs/SM fits 184 KB

template<int EPI>
__global__ void __launch_bounds__(256, 3) gemm_hf(
    const __half* __restrict__ Ahi, const __half* __restrict__ Alo,
    const __half* __restrict__ Bhi, const __half* __restrict__ Blo,
    const float* __restrict__ bias, float* __restrict__ Cf,
    __half* __restrict__ Chi, __half* __restrict__ Clo,
    int M, int N, int K, int n3lim, int alo_lo, int alo_hi,
    int wlo_lo, int wlo_hi)
{
    extern __shared__ char smem[];
    const int tid = threadIdx.x;
    const int lane = tid & 31;
    const int warp = tid >> 5;
    const int wm = warp >> 2;        // 0..1 (32 rows each)
    const int wn = warp & 3;         // 0..3 (32 cols each)
    const int row0 = blockIdx.y * 64;
    const int col0 = blockIdx.x * 128;
    const bool use3 = (col0 < n3lim);
    const bool ualo = (col0 >= alo_lo) && (col0 < alo_hi);

    // A loader: 64 rows x 32 halves; 4 cp16 chunks per row -> 1 chunk/thread/plane
    const int arow = tid >> 2;          // 0..63
    const int acol = (tid & 3);         // chunk 0..3 (8 halves each)
    // B loader: 128 rows x 32 halves; 2 chunks/thread
    const int brow = tid >> 1;          // 0..127
    const int bq = (tid & 1) * 2;       // chunk base 0 or 2

    auto issue = [&](int kc, int s) {
        char* stg = smem + s * GSTAGE;
        const uint32_t base = s2u(stg);
        const uint32_t sA = base + (uint32_t)arow * GST + acol * 16;
        const size_t gA = (size_t)(row0 + arow) * K + kc * 32 + acol * 8;
        cp16(sA, Ahi + gA);
        if (ualo) cp16(sA + GTA, Alo + gA);
        const uint32_t sB = base + 2 * GTA + (uint32_t)brow * GST + bq * 16;
        const size_t gB = (size_t)(col0 + brow) * K + kc * 32 + bq * 8;
        cp16(sB, Bhi + gB);
        cp16(sB + 16, Bhi + gB + 8);
        if (use3) {
            cp16(sB + GTB, Blo + gB);
            cp16(sB + GTB + 16, Blo + gB + 8);
        }
    };

    float acc[2][4][4];
#pragma unroll
    for (int i = 0; i < 2; i++)
#pragma unroll
        for (int j = 0; j < 4; j++)
#pragma unroll
            for (int e = 0; e < 4; e++) acc[i][j][e] = 0.f;

    const uint32_t fragoff = (uint32_t)(lane & 15) * GST + (uint32_t)(lane >> 4) * 16;

    issue(0, 0);
    CP_COMMIT();

    const int nch = K / 32;
    for (int kc = 0; kc < nch; kc++) {
        const int s = kc & 1;
        CP_WAIT0();
        __syncthreads();
        if (kc + 1 < nch) {
            issue(kc + 1, s ^ 1);
            CP_COMMIT();
        }
        char* stg = smem + s * GSTAGE;
        const uint32_t uAhi = s2u(stg);
        const uint32_t uAlo = uAhi + GTA;
        const uint32_t uBhi = uAhi + 2 * GTA;
        const uint32_t uBlo = uBhi + GTB;

#pragma unroll
        for (int ks = 0; ks < 2; ks++) {
            const uint32_t kb = (uint32_t)ks * 32;
            uint32_t bh[4][2], bl[4][2];
#pragma unroll
            for (int ntp = 0; ntp < 2; ntp++) {
                const uint32_t boff = (uint32_t)(wn * 32 + ntp * 16) * GST + kb + fragoff;
                uint32_t m[4];
                ldmx4(m, uBhi + boff);
                bh[ntp * 2 + 0][0] = m[0]; bh[ntp * 2 + 1][0] = m[1];
                bh[ntp * 2 + 0][1] = m[2]; bh[ntp * 2 + 1][1] = m[3];
                if (use3) {
                    ldmx4(m, uBlo + boff);
                    bl[ntp * 2 + 0][0] = m[0]; bl[ntp * 2 + 1][0] = m[1];
                    bl[ntp * 2 + 0][1] = m[2]; bl[ntp * 2 + 1][1] = m[3];
                }
            }
            uint32_t ah[2][4];
#pragma unroll
            for (int mt = 0; mt < 2; mt++) {
                const uint32_t aoff = (uint32_t)(wm * 32 + mt * 16) * GST + kb + fragoff;
                ldmx4(ah[mt], uAhi + aoff);
            }
            // PASS 1: ah·bh (acc distance 8)
#pragma unroll
            for (int mt = 0; mt < 2; mt++)
#pragma unroll
                for (int nt = 0; nt < 4; nt++)
                    mma_f16(acc[mt][nt], ah[mt], bh[nt]);
            // PASS 2: ah·bl
            if (use3) {
#pragma unroll
                for (int mt = 0; mt < 2; mt++)
#pragma unroll
                    for (int nt = 0; nt < 4; nt++)
                        mma_f16(acc[mt][nt], ah[mt], bl[nt]);
            }
            // PASS 3: al·bh
            if (ualo) {
#pragma unroll
                for (int mt = 0; mt < 2; mt++) {
                    const uint32_t aoff = (uint32_t)(wm * 32 + mt * 16) * GST + kb + fragoff;
                    uint32_t al[4];
                    ldmx4(al, uAlo + aoff);
#pragma unroll
                    for (int nt = 0; nt < 4; nt++)
                        mma_f16(acc[mt][nt], al, bh[nt]);
                }
            }
        }
    }

    // epilogue
    const bool wlo = (col0 >= wlo_lo) && (col0 < wlo_hi);
#pragma unroll
    for (int mt = 0; mt < 2; mt++) {
        const int r = row0 + wm * 32 + mt * 16 + (lane >> 2);
#pragma unroll
        for (int nt = 0; nt < 4; nt++) {
            const int c = col0 + wn * 32 + nt * 8 + (lane & 3) * 2;
            const float bx = bias[c];
            const float by = bias[c + 1];
            const float f0 = acc[mt][nt][0] + bx;
            const float f1 = acc[mt][nt][1] + by;
            const float f2 = acc[mt][nt][2] + bx;
            const float f3 = acc[mt][nt][3] + by;
            if (EPI == 0) {
                *(float2*)(Cf + (size_t)r * N + c) = make_float2(f0, f1);
                *(float2*)(Cf + (size_t)(r + 8) * N + c) = make_float2(f2, f3);
            } else {
                uint32_t h0, l0, h1, l1;
                cvt_packh(f0, f1, h0, l0);
                cvt_packh(f2, f3, h1, l1);
                const size_t i0 = ((size_t)r * N + c) / 2;
                const size_t i1 = ((size_t)(r + 8) * N + c) / 2;
                ((uint32_t*)Chi)[i0] = h0;
                ((uint32_t*)Chi)[i1] = h1;
                if (wlo) {
                    ((uint32_t*)Clo)[i0] = l0;
                    ((uint32_t*)Clo)[i1] = l1;
                }
            }
        }
    }
}

// ---------------------------------------------------------------------------
// Flash attention from fp16 qkv planes (identical to R11).
// QK: 3-MMA (qh·Khi + qh·Klo + ql·Khi). PV: 1-MMA. Output: hi plane only.
// ---------------------------------------------------------------------------
#define AST 144
#define ATL (64 * AST)
#define ASTG (3 * ATL)              // Khi,Klo,Vhi = 27648
#define ATTN_SMEM (ASTG + 2 * 128 * AST)   // 64512

__global__ void __launch_bounds__(256) flash2(
    const __half* __restrict__ qhi, const __half* __restrict__ qlo,
    __half* __restrict__ ohi)
{
    extern __shared__ char smem[];
    const int tid = threadIdx.x;
    const int lane = tid & 31;
    const int warp = tid >> 5;
    const int qt = blockIdx.x;
    const int bh = blockIdx.y;
    const int b = bh >> 4;
    const int h = bh & 15;

    const uint32_t sb = s2u(smem);
    const uint32_t fragoff = (uint32_t)(lane & 15) * AST + (uint32_t)(lane >> 4) * 16;
    const size_t headoff = (size_t)h * DHd;

    const int krow = tid >> 2;
    const int kcc = (tid & 3) * 2;
    auto issueKV = [&](int kb, int s) {
        const uint32_t sB = sb + s * ASTG + (uint32_t)krow * AST + kcc * 16;
        const size_t g = ((size_t)b * Ss + kb * 64 + krow) * N1 + headoff + kcc * 8;
        cp16(sB,                 qhi + g + Dd);       // K hi
        cp16(sB + 16,            qhi + g + Dd + 8);
        cp16(sB + ATL,           qlo + g + Dd);       // K lo
        cp16(sB + ATL + 16,      qlo + g + Dd + 8);
        cp16(sB + 2 * ATL,       qhi + g + 2 * Dd);   // V hi
        cp16(sB + 2 * ATL + 16,  qhi + g + 2 * Dd + 8);
    };

    issueKV(0, 0);
    CP_COMMIT();
    {
        const int qrow = tid >> 1;
        const int q4 = (tid & 1) * 4;
        const uint32_t sQh = sb + ASTG + (uint32_t)qrow * AST + q4 * 16;
        const uint32_t sQl = sQh + 128 * AST;
        const size_t g = ((size_t)b * Ss + qt * 128 + qrow) * N1 + headoff + q4 * 8;
#pragma unroll
        for (int i = 0; i < 4; i++) {
            cp16(sQh + i * 16, qhi + g + i * 8);
            cp16(sQl + i * 16, qlo + g + i * 8);
        }
    }
    CP_COMMIT();
    CP_WAIT0();
    __syncthreads();

    uint32_t qh[4][4], ql[4][4];
    {
        const uint32_t uQh = sb + ASTG;
        const uint32_t uQl = uQh + 128 * AST;
#pragma unroll
        for (int j = 0; j < 4; j++) {
            const uint32_t aoff = (uint32_t)(warp * 16) * AST + j * 32 + fragoff;
            ldmx4(qh[j], uQh + aoff);
            ldmx4(ql[j], uQl + aoff);
        }
    }

    float o[8][4];
    float m0 = -1e30f, m1 = -1e30f, l0 = 0.f, l1 = 0.f;
#pragma unroll
    for (int i = 0; i < 8; i++)
#pragma unroll
        for (int e = 0; e < 4; e++) o[i][e] = 0.f;

    for (int kb = 0; kb < Ss / 64; kb++) {
        const int s = kb & 1;
        if (kb > 0) CP_WAIT0();
        __syncthreads();
        if (kb + 1 < Ss / 64) {
            issueKV(kb + 1, s ^ 1);
            CP_COMMIT();
        }
        const uint32_t uKhi = sb + s * ASTG;
        const uint32_t uKlo = uKhi + ATL;
        const uint32_t uVhi = uKhi + 2 * ATL;

        float sc[8][4];
#pragma unroll
        for (int i = 0; i < 8; i++)
#pragma unroll
            for (int e = 0; e < 4; e++) sc[i][e] = 0.f;

#pragma unroll
        for (int j = 0; j < 4; j++) {
#pragma unroll
            for (int g = 0; g < 4; g++) {
                const uint32_t boff = (uint32_t)(g * 16) * AST + j * 32 + fragoff;
                uint32_t mh[4];
                ldmx4(mh, uKhi + boff);
                uint32_t b0[2] = {mh[0], mh[2]}, b1[2] = {mh[1], mh[3]};
                mma_f16(sc[2 * g + 0], qh[j], b0);
                mma_f16(sc[2 * g + 1], qh[j], b1);
            }
#pragma unroll
            for (int g = 0; g < 4; g++) {
                const uint32_t boff = (uint32_t)(g * 16) * AST + j * 32 + fragoff;
                uint32_t ml[4];
                ldmx4(ml, uKlo + boff);
                uint32_t b0[2] = {ml[0], ml[2]}, b1[2] = {ml[1], ml[3]};
                mma_f16(sc[2 * g + 0], qh[j], b0);
                mma_f16(sc[2 * g + 1], qh[j], b1);
            }
#pragma unroll
            for (int g = 0; g < 4; g++) {
                const uint32_t boff = (uint32_t)(g * 16) * AST + j * 32 + fragoff;
                uint32_t mh[4];
                ldmx4(mh, uKhi + boff);
                uint32_t b0[2] = {mh[0], mh[2]}, b1[2] = {mh[1], mh[3]};
                mma_f16(sc[2 * g + 0], ql[j], b0);
                mma_f16(sc[2 * g + 1], ql[j], b1);
            }
        }

        // ---- online softmax ----
        float mx0 = -1e30f, mx1 = -1e30f;
#pragma unroll
        for (int i = 0; i < 8; i++) {
            mx0 = fmaxf(mx0, fmaxf(sc[i][0], sc[i][1]));
            mx1 = fmaxf(mx1, fmaxf(sc[i][2], sc[i][3]));
        }
        mx0 = fmaxf(mx0, __shfl_xor_sync(0xffffffffu, mx0, 1));
        mx0 = fmaxf(mx0, __shfl_xor_sync(0xffffffffu, mx0, 2));
        mx1 = fmaxf(mx1, __shfl_xor_sync(0xffffffffu, mx1, 1));
        mx1 = fmaxf(mx1, __shfl_xor_sync(0xffffffffu, mx1, 2));
        const float mn0 = fmaxf(m0, mx0);
        const float mn1 = fmaxf(m1, mx1);
        const float c0 = __expf(m0 - mn0);
        const float c1 = __expf(m1 - mn1);
        float rs0 = 0.f, rs1 = 0.f;
#pragma unroll
        for (int i = 0; i < 8; i++) {
            sc[i][0] = __expf(sc[i][0] - mn0);
            sc[i][1] = __expf(sc[i][1] - mn0);
            sc[i][2] = __expf(sc[i][2] - mn1);
            sc[i][3] = __expf(sc[i][3] - mn1);
            rs0 += sc[i][0] + sc[i][1];
            rs1 += sc[i][2] + sc[i][3];
        }
        rs0 += __shfl_xor_sync(0xffffffffu, rs0, 1);
        rs0 += __shfl_xor_sync(0xffffffffu, rs0, 2);
        rs1 += __shfl_xor_sync(0xffffffffu, rs1, 1);
        rs1 += __shfl_xor_sync(0xffffffffu, rs1, 2);
        l0 = l0 * c0 + rs0;
        l1 = l1 * c1 + rs1;
        m0 = mn0;
        m1 = mn1;
#pragma unroll
        for (int i = 0; i < 8; i++) {
            o[i][0] *= c0; o[i][1] *= c0;
            o[i][2] *= c1; o[i][3] *= c1;
        }

        uint32_t ph[4][4];
#pragma unroll
        for (int j = 0; j < 4; j++) {
            ph[j][0] = pack_h(sc[2 * j][0],     sc[2 * j][1]);
            ph[j][1] = pack_h(sc[2 * j][2],     sc[2 * j][3]);
            ph[j][2] = pack_h(sc[2 * j + 1][0], sc[2 * j + 1][1]);
            ph[j][3] = pack_h(sc[2 * j + 1][2], sc[2 * j + 1][3]);
        }

#pragma unroll
        for (int j = 0; j < 4; j++) {
#pragma unroll
            for (int g = 0; g < 4; g++) {
                const uint32_t voff = (uint32_t)(j * 16) * AST + g * 32 + fragoff;
                uint32_t mh[4];
                ldmx4t(mh, uVhi + voff);
                uint32_t b0[2] = {mh[0], mh[1]}, b1[2] = {mh[2], mh[3]};
                mma_f16(o[2 * g + 0], ph[j], b0);
                mma_f16(o[2 * g + 1], ph[j], b1);
            }
        }
    }

    const float inv0 = 1.f / l0;
    const float inv1 = 1.f / l1;
    const int r0 = qt * 128 + warp * 16 + (lane >> 2);
    const size_t base0 = ((size_t)b * Ss + r0) * Dd + headoff + (lane & 3) * 2;
    const size_t base1 = base0 + (size_t)8 * Dd;
#pragma unroll
    for (int nt = 0; nt < 8; nt++) {
        ((uint32_t*)ohi)[(base0 + nt * 8) / 2] = pack_h(o[nt][0] * inv0, o[nt][1] * inv0);
        ((uint32_t*)ohi)[(base1 + nt * 8) / 2] = pack_h(o[nt][2] * inv1, o[nt][3] * inv1);
    }
}

// ---------------------------------------------------------------------------
extern "C" void kernel_launch(void* const* d_in, const int* in_sizes, int n_in,
                              void* d_out, int out_size)
{
    (void)in_sizes; (void)n_in; (void)out_size;
    const float* x  = (const float*)d_in[0];
    const float* w1 = (const float*)d_in[1];
    const float* b1 = (const float*)d_in[2];
    const float* w2 = (const float*)d_in[3];
    const float* b2 = (const float*)d_in[4];
    float* out = (float*)d_out;

    __half *xhi, *xlo, *w1hi, *w1lo, *w2hi, *qhi, *qlo, *ahi;
    cudaGetSymbolAddress((void**)&xhi, g_xhi);
    cudaGetSymbolAddress((void**)&xlo, g_xlo);
    cudaGetSymbolAddress((void**)&w1hi, g_w1hi);
    cudaGetSymbolAddress((void**)&w1lo, g_w1lo);
    cudaGetSymbolAddress((void**)&w2hi, g_w2hi);
    cudaGetSymbolAddress((void**)&qhi, g_qkvhi);
    cudaGetSymbolAddress((void**)&qlo, g_qkvlo);
    cudaGetSymbolAddress((void**)&ahi, g_ahi);

    cudaFuncSetAttribute(gemm_hf<0>, cudaFuncAttributeMaxDynamicSharedMemorySize, GEMM_SMEM);
    cudaFuncSetAttribute(gemm_hf<1>, cudaFuncAttributeMaxDynamicSharedMemorySize, GEMM_SMEM);
    cudaFuncSetAttribute(flash2, cudaFuncAttributeMaxDynamicSharedMemorySize, ATTN_SMEM);

    // pre-convert
    split_f32<<<(MM * Dd / 2 + 255) / 256, 256>>>(x, xhi, xlo, MM * Dd / 2);
    transpose_split<<<dim3(N1 / 32, Dd / 64), 256>>>(w1, w1hi, w1lo, Dd, N1, 1);
    transpose_split<<<dim3(Dd / 32, Dd / 64), 256>>>(w2, w2hi, nullptr, Dd, Dd, 0);

    // 1) QKV projection (64-row tiles for occupancy):
    //    Q,K cols [0,2048): 3-MMA, hi+lo out; V cols [2048,3072): 1-MMA, hi out
    gemm_hf<1><<<dim3(N1 / 128, MM / 64), 256, GEMM_SMEM>>>(
        xhi, xlo, w1hi, w1lo, b1, nullptr, qhi, qlo, MM, N1, Dd,
        /*n3lim=*/2 * Dd, /*alo=*/0, 2 * Dd, /*wlo=*/0, 2 * Dd);
    // 2) attention (QK 3-MMA, PV 1-MMA) -> a hi plane
    flash2<<<dim3(Ss / 128, Bb * Hh), 256, ATTN_SMEM>>>(qhi, qlo, ahi);
    // 3) output projection (1-MMA) -> fp32 out
    gemm_hf<0><<<dim3(Dd / 128, MM / 64), 256, GEMM_SMEM>>>(
        ahi, nullptr, w2hi, nullptr, b2, out, nullptr, nullptr, MM, Dd, Dd,
        /*n3lim=*/0, /*alo=*/0, 0, /*wlo=*/0, 0);
}

// round 14
// speedup vs baseline: 1.2341x; 1.0820x over previous
#include <cuda_runtime.h>
#include <cuda_fp16.h>
#include <cstdint>

// Problem constants
#define Bb 4
#define Ss 2048
#define Dd 1024
#define Hh 16
#define DHd 64
#define MM (Bb * Ss)          // 8192
#define N1 (3 * Dd)           // 3072

// ---------------- global scratch (fp16 hi/lo planes) ----------------
__device__ __half g_xhi[(size_t)MM * Dd];
__device__ __half g_xlo[(size_t)MM * Dd];
__device__ __half g_w1hi[(size_t)N1 * Dd];    // [n][k]
__device__ __half g_w1lo[(size_t)N1 * Dd];
__device__ __half g_w2hi[(size_t)Dd * Dd];    // [n][k]
__device__ __half g_qkvhi[(size_t)MM * N1];
__device__ __half g_qkvlo[(size_t)MM * N1];   // lo valid for K cols only
__device__ __half g_ahi[(size_t)MM * Dd];

// ---------------- helpers ----------------
__device__ __forceinline__ uint32_t s2u(const void* p) {
    uint32_t a;
    asm("{ .reg .u64 t; cvta.to.shared.u64 t, %1; cvt.u32.u64 %0, t; }" : "=r"(a) : "l"(p));
    return a;
}
__device__ __forceinline__ void cp16(uint32_t saddr, const void* gaddr) {
    asm volatile("cp.async.cg.shared.global [%0], [%1], 16;" :: "r"(saddr), "l"(gaddr));
}
#define CP_COMMIT() asm volatile("cp.async.commit_group;" ::: "memory")
#define CP_WAIT0()  asm volatile("cp.async.wait_group 0;" ::: "memory")

__device__ __forceinline__ void ldmx4(uint32_t* r, uint32_t addr) {
    asm volatile("ldmatrix.sync.aligned.m8n8.x4.shared.b16 {%0,%1,%2,%3}, [%4];"
        : "=r"(r[0]), "=r"(r[1]), "=r"(r[2]), "=r"(r[3]) : "r"(addr));
}
__device__ __forceinline__ void ldmx4t(uint32_t* r, uint32_t addr) {
    asm volatile("ldmatrix.sync.aligned.m8n8.x4.trans.shared.b16 {%0,%1,%2,%3}, [%4];"
        : "=r"(r[0]), "=r"(r[1]), "=r"(r[2]), "=r"(r[3]) : "r"(addr));
}
__device__ __forceinline__ void mma_f16(float* c, const uint32_t* a, const uint32_t* b) {
    asm volatile("mma.sync.aligned.m16n8k16.row.col.f32.f16.f16.f32 "
        "{%0,%1,%2,%3}, {%4,%5,%6,%7}, {%8,%9}, {%0,%1,%2,%3};"
        : "+f"(c[0]), "+f"(c[1]), "+f"(c[2]), "+f"(c[3])
        : "r"(a[0]), "r"(a[1]), "r"(a[2]), "r"(a[3]), "r"(b[0]), "r"(b[1]));
}
// fp32 pair -> packed fp16 hi pair + fp16 lo pair (hi = rn(f), lo = rn(f - hi))
__device__ __forceinline__ void cvt_packh(float f0, float f1, uint32_t& hi, uint32_t& lo) {
    __half h0 = __float2half_rn(f0);
    __half h1 = __float2half_rn(f1);
    __half l0 = __float2half_rn(f0 - __half2float(h0));
    __half l1 = __float2half_rn(f1 - __half2float(h1));
    hi = ((uint32_t)__half_as_ushort(h1) << 16) | (uint32_t)__half_as_ushort(h0);
    lo = ((uint32_t)__half_as_ushort(l1) << 16) | (uint32_t)__half_as_ushort(l0);
}
__device__ __forceinline__ uint32_t pack_h(float f0, float f1) {
    __half h0 = __float2half_rn(f0);
    __half h1 = __float2half_rn(f1);
    return ((uint32_t)__half_as_ushort(h1) << 16) | (uint32_t)__half_as_ushort(h0);
}

// ---------------- pre-convert kernels ----------------
__global__ void __launch_bounds__(256) split_f32(
    const float* __restrict__ src, __half* __restrict__ hi,
    __half* __restrict__ lo, int n2)
{
    int i = blockIdx.x * 256 + threadIdx.x;
    if (i >= n2) return;
    float2 v = *(const float2*)(src + 2 * i);
    uint32_t h, l;
    cvt_packh(v.x, v.y, h, l);
    ((uint32_t*)hi)[i] = h;
    ((uint32_t*)lo)[i] = l;
}

// W[K][N] fp32 -> Wt hi(/lo) [N][K] fp16
__global__ void __launch_bounds__(256) transpose_split(
    const float* __restrict__ W, __half* __restrict__ Whi,
    __half* __restrict__ Wlo, int K, int N, int write_lo)
{
    __shared__ float sm[64][33];
    const int tid = threadIdx.x;
    const int n0 = blockIdx.x * 32;
    const int k0 = blockIdx.y * 64;
#pragma unroll
    for (int p = 0; p < 8; p++) {
        const int k = p * 8 + (tid >> 5);
        const int n = tid & 31;
        sm[k][n] = W[(size_t)(k0 + k) * N + n0 + n];
    }
    __syncthreads();
#pragma unroll
    for (int p = 0; p < 4; p++) {
        const int n = p * 8 + (tid >> 5);
        const int kp = tid & 31;
        uint32_t h, l;
        cvt_packh(sm[2 * kp][n], sm[2 * kp + 1][n], h, l);
        const size_t idx = ((size_t)(n0 + n) * K + k0) / 2 + kp;
        ((uint32_t*)Whi)[idx] = h;
        if (write_lo) ((uint32_t*)Wlo)[idx] = l;
    }
}

// ---------------------------------------------------------------------------
// GEMM from fp16 planes (R11 shape: 128x128 tile, BK=32, 2 CTAs/SM).
// Passes: ah·bh always; ah·bl when col0 < n3lim; al·bh in [alo_lo, alo_hi).
// EPI: 0 -> fp32 C, 1 -> fp16 hi plane (+lo when col0 in [wlo_lo, wlo_hi)).
// ---------------------------------------------------------------------------
#define GST 80
#define GTILE (128 * GST)
#define GSTAGE (4 * GTILE)
#define GEMM_SMEM (2 * GSTAGE)

template<int EPI>
__global__ void __launch_bounds__(256, 2) gemm_hf(
    const __half* __restrict__ Ahi, const __half* __restrict__ Alo,
    const __half* __restrict__ Bhi, const __half* __restrict__ Blo,
    const float* __restrict__ bias, float* __restrict__ Cf,
    __half* __restrict__ Chi, __half* __restrict__ Clo,
    int M, int N, int K, int n3lim, int alo_lo, int alo_hi,
    int wlo_lo, int wlo_hi)
{
    extern __shared__ char smem[];
    const int tid = threadIdx.x;
    const int lane = tid & 31;
    const int warp = tid >> 5;
    const int wm = warp >> 2;
    const int wn = warp & 3;
    const int row0 = blockIdx.y * 128;
    const int col0 = blockIdx.x * 128;
    const bool use3 = (col0 < n3lim);
    const bool ualo = (col0 >= alo_lo) && (col0 < alo_hi);

    const int lrow = tid >> 1;
    const int lq = (tid & 1) * 2;

    auto issue = [&](int kc, int s) {
        char* stg = smem + s * GSTAGE;
        const uint32_t sA = s2u(stg) + (uint32_t)lrow * GST + lq * 16;
        const size_t gOffA = (size_t)(row0 + lrow) * K + kc * 32 + lq * 8;
        cp16(sA, Ahi + gOffA);
        cp16(sA + 16, Ahi + gOffA + 8);
        if (ualo) {
            cp16(sA + GTILE, Alo + gOffA);
            cp16(sA + GTILE + 16, Alo + gOffA + 8);
        }
        const size_t gOffB = (size_t)(col0 + lrow) * K + kc * 32 + lq * 8;
        cp16(sA + 2 * GTILE, Bhi + gOffB);
        cp16(sA + 2 * GTILE + 16, Bhi + gOffB + 8);
        if (use3) {
            cp16(sA + 3 * GTILE, Blo + gOffB);
            cp16(sA + 3 * GTILE + 16, Blo + gOffB + 8);
        }
    };

    float acc[4][4][4];
#pragma unroll
    for (int i = 0; i < 4; i++)
#pragma unroll
        for (int j = 0; j < 4; j++)
#pragma unroll
            for (int e = 0; e < 4; e++) acc[i][j][e] = 0.f;

    const uint32_t fragoff = (uint32_t)(lane & 15) * GST + (uint32_t)(lane >> 4) * 16;

    issue(0, 0);
    CP_COMMIT();

    const int nch = K / 32;
    for (int kc = 0; kc < nch; kc++) {
        const int s = kc & 1;
        CP_WAIT0();
        __syncthreads();
        if (kc + 1 < nch) {
            issue(kc + 1, s ^ 1);
            CP_COMMIT();
        }
        char* stg = smem + s * GSTAGE;
        const uint32_t uAhi = s2u(stg);
        const uint32_t uAlo = uAhi + GTILE;
        const uint32_t uBhi = uAhi + 2 * GTILE;
        const uint32_t uBlo = uAhi + 3 * GTILE;

#pragma unroll
        for (int ks = 0; ks < 2; ks++) {
            const uint32_t kb = (uint32_t)ks * 32;
            uint32_t bh[4][2], bl[4][2];
#pragma unroll
            for (int ntp = 0; ntp < 2; ntp++) {
                const uint32_t boff = (uint32_t)(wn * 32 + ntp * 16) * GST + kb + fragoff;
                uint32_t m[4];
                ldmx4(m, uBhi + boff);
                bh[ntp * 2 + 0][0] = m[0]; bh[ntp * 2 + 1][0] = m[1];
                bh[ntp * 2 + 0][1] = m[2]; bh[ntp * 2 + 1][1] = m[3];
                if (use3) {
                    ldmx4(m, uBlo + boff);
                    bl[ntp * 2 + 0][0] = m[0]; bl[ntp * 2 + 1][0] = m[1];
                    bl[ntp * 2 + 0][1] = m[2]; bl[ntp * 2 + 1][1] = m[3];
                }
            }
            uint32_t ah[4][4];
#pragma unroll
            for (int mt = 0; mt < 4; mt++) {
                const uint32_t aoff = (uint32_t)(wm * 64 + mt * 16) * GST + kb + fragoff;
                ldmx4(ah[mt], uAhi + aoff);
            }
            // PASS 1: ah·bh
#pragma unroll
            for (int mt = 0; mt < 4; mt++)
#pragma unroll
                for (int nt = 0; nt < 4; nt++)
                    mma_f16(acc[mt][nt], ah[mt], bh[nt]);
            // PASS 2: ah·bl
            if (use3) {
#pragma unroll
                for (int mt = 0; mt < 4; mt++)
#pragma unroll
                    for (int nt = 0; nt < 4; nt++)
                        mma_f16(acc[mt][nt], ah[mt], bl[nt]);
            }
            // PASS 3: al·bh
            if (ualo) {
#pragma unroll
                for (int mt = 0; mt < 4; mt++) {
                    const uint32_t aoff = (uint32_t)(wm * 64 + mt * 16) * GST + kb + fragoff;
                    uint32_t al[4];
                    ldmx4(al, uAlo + aoff);
#pragma unroll
                    for (int nt = 0; nt < 4; nt++)
                        mma_f16(acc[mt][nt], al, bh[nt]);
                }
            }
        }
    }

    // epilogue
    const bool wlo = (col0 >= wlo_lo) && (col0 < wlo_hi);
#pragma unroll
    for (int mt = 0; mt < 4; mt++) {
        const int r = row0 + wm * 64 + mt * 16 + (lane >> 2);
#pragma unroll
        for (int nt = 0; nt < 4; nt++) {
            const int c = col0 + wn * 32 + nt * 8 + (lane & 3) * 2;
            const float bx = bias[c];
            const float by = bias[c + 1];
            const float f0 = acc[mt][nt][0] + bx;
            const float f1 = acc[mt][nt][1] + by;
            const float f2 = acc[mt][nt][2] + bx;
            const float f3 = acc[mt][nt][3] + by;
            if (EPI == 0) {
                *(float2*)(Cf + (size_t)r * N + c) = make_float2(f0, f1);
                *(float2*)(Cf + (size_t)(r + 8) * N + c) = make_float2(f2, f3);
            } else {
                uint32_t h0, l0, h1, l1;
                cvt_packh(f0, f1, h0, l0);
                cvt_packh(f2, f3, h1, l1);
                const size_t i0 = ((size_t)r * N + c) / 2;
                const size_t i1 = ((size_t)(r + 8) * N + c) / 2;
                ((uint32_t*)Chi)[i0] = h0;
                ((uint32_t*)Chi)[i1] = h1;
                if (wlo) {
                    ((uint32_t*)Clo)[i0] = l0;
                    ((uint32_t*)Clo)[i1] = l1;
                }
            }
        }
    }
}

// ---------------------------------------------------------------------------
// Flash attention from fp16 qkv planes.
// QK: 2-MMA (qh·Khi + qh·Klo) — q-lo dead (error cut, calibrated from R10).
// PV: 1-MMA (P hi, V hi). Output: hi plane only.
// ---------------------------------------------------------------------------
#define AST 144
#define ATL (64 * AST)
#define ASTG (3 * ATL)              // Khi,Klo,Vhi = 27648
#define ATTN_SMEM (2 * ASTG)        // 55296 (Q-hi staging overlaps stage1)

__global__ void __launch_bounds__(256) flash2(
    const __half* __restrict__ qhi, const __half* __restrict__ qlo,
    __half* __restrict__ ohi)
{
    (void)qlo;
    extern __shared__ char smem[];
    const int tid = threadIdx.x;
    const int lane = tid & 31;
    const int warp = tid >> 5;
    const int qt = blockIdx.x;
    const int bh = blockIdx.y;
    const int b = bh >> 4;
    const int h = bh & 15;

    const uint32_t sb = s2u(smem);
    const uint32_t fragoff = (uint32_t)(lane & 15) * AST + (uint32_t)(lane >> 4) * 16;
    const size_t headoff = (size_t)h * DHd;

    const int krow = tid >> 2;
    const int kcc = (tid & 3) * 2;
    auto issueKV = [&](int kb, int s) {
        const uint32_t sB = sb + s * ASTG + (uint32_t)krow * AST + kcc * 16;
        const size_t g = ((size_t)b * Ss + kb * 64 + krow) * N1 + headoff + kcc * 8;
        cp16(sB,                 qhi + g + Dd);       // K hi
        cp16(sB + 16,            qhi + g + Dd + 8);
        cp16(sB + ATL,           qlo + g + Dd);       // K lo
        cp16(sB + ATL + 16,      qlo + g + Dd + 8);
        cp16(sB + 2 * ATL,       qhi + g + 2 * Dd);   // V hi
        cp16(sB + 2 * ATL + 16,  qhi + g + 2 * Dd + 8);
    };

    // preload: K/V block0 -> stage0; Q-hi -> region above stage0 (overlaps
    // stage1; safe: Q is consumed into registers before stage1 is written)
    issueKV(0, 0);
    CP_COMMIT();
    {
        const int qrow = tid >> 1;
        const int q4 = (tid & 1) * 4;
        const uint32_t sQh = sb + ASTG + (uint32_t)qrow * AST + q4 * 16;
        const size_t g = ((size_t)b * Ss + qt * 128 + qrow) * N1 + headoff + q4 * 8;
#pragma unroll
        for (int i = 0; i < 4; i++)
            cp16(sQh + i * 16, qhi + g + i * 8);
    }
    CP_COMMIT();
    CP_WAIT0();
    __syncthreads();

    // Q-hi fragments (extracted before stage1 is ever written)
    uint32_t qh[4][4];
    {
        const uint32_t uQh = sb + ASTG;
#pragma unroll
        for (int j = 0; j < 4; j++) {
            const uint32_t aoff = (uint32_t)(warp * 16) * AST + j * 32 + fragoff;
            ldmx4(qh[j], uQh + aoff);
        }
    }

    float o[8][4];
    float m0 = -1e30f, m1 = -1e30f, l0 = 0.f, l1 = 0.f;
#pragma unroll
    for (int i = 0; i < 8; i++)
#pragma unroll
        for (int e = 0; e < 4; e++) o[i][e] = 0.f;

    for (int kb = 0; kb < Ss / 64; kb++) {
        const int s = kb & 1;
        if (kb > 0) CP_WAIT0();
        __syncthreads();
        if (kb + 1 < Ss / 64) {
            issueKV(kb + 1, s ^ 1);
            CP_COMMIT();
        }
        const uint32_t uKhi = sb + s * ASTG;
        const uint32_t uKlo = uKhi + ATL;
        const uint32_t uVhi = uKhi + 2 * ATL;

        // ---- S = Q K^T (2-MMA, pass-major: acc distance 8) ----
        float sc[8][4];
#pragma unroll
        for (int i = 0; i < 8; i++)
#pragma unroll
            for (int e = 0; e < 4; e++) sc[i][e] = 0.f;

#pragma unroll
        for (int j = 0; j < 4; j++) {
            // pass 1: qh · Khi
#pragma unroll
            for (int g = 0; g < 4; g++) {
                const uint32_t boff = (uint32_t)(g * 16) * AST + j * 32 + fragoff;
                uint32_t mh[4];
                ldmx4(mh, uKhi + boff);
                uint32_t b0[2] = {mh[0], mh[2]}, b1[2] = {mh[1], mh[3]};
                mma_f16(sc[2 * g + 0], qh[j], b0);
                mma_f16(sc[2 * g + 1], qh[j], b1);
            }
            // pass 2: qh · Klo
#pragma unroll
            for (int g = 0; g < 4; g++) {
                const uint32_t boff = (uint32_t)(g * 16) * AST + j * 32 + fragoff;
                uint32_t ml[4];
                ldmx4(ml, uKlo + boff);
                uint32_t b0[2] = {ml[0], ml[2]}, b1[2] = {ml[1], ml[3]};
                mma_f16(sc[2 * g + 0], qh[j], b0);
                mma_f16(sc[2 * g + 1], qh[j], b1);
            }
        }

        // ---- online softmax ----
        float mx0 = -1e30f, mx1 = -1e30f;
#pragma unroll
        for (int i = 0; i < 8; i++) {
            mx0 = fmaxf(mx0, fmaxf(sc[i][0], sc[i][1]));
            mx1 = fmaxf(mx1, fmaxf(sc[i][2], sc[i][3]));
        }
        mx0 = fmaxf(mx0, __shfl_xor_sync(0xffffffffu, mx0, 1));
        mx0 = fmaxf(mx0, __shfl_xor_sync(0xffffffffu, mx0, 2));
        mx1 = fmaxf(mx1, __shfl_xor_sync(0xffffffffu, mx1, 1));
        mx1 = fmaxf(mx1, __shfl_xor_sync(0xffffffffu, mx1, 2));
        const float mn0 = fmaxf(m0, mx0);
        const float mn1 = fmaxf(m1, mx1);
        const float c0 = __expf(m0 - mn0);
        const float c1 = __expf(m1 - mn1);
        float rs0 = 0.f, rs1 = 0.f;
#pragma unroll
        for (int i = 0; i < 8; i++) {
            sc[i][0] = __expf(sc[i][0] - mn0);
            sc[i][1] = __expf(sc[i][1] - mn0);
            sc[i][2] = __expf(sc[i][2] - mn1);
            sc[i][3] = __expf(sc[i][3] - mn1);
            rs0 += sc[i][0] + sc[i][1];
            rs1 += sc[i][2] + sc[i][3];
        }
        rs0 += __shfl_xor_sync(0xffffffffu, rs0, 1);
        rs0 += __shfl_xor_sync(0xffffffffu, rs0, 2);
        rs1 += __shfl_xor_sync(0xffffffffu, rs1, 1);
        rs1 += __shfl_xor_sync(0xffffffffu, rs1, 2);
        l0 = l0 * c0 + rs0;
        l1 = l1 * c1 + rs1;
        m0 = mn0;
        m1 = mn1;
#pragma unroll
        for (int i = 0; i < 8; i++) {
            o[i][0] *= c0; o[i][1] *= c0;
            o[i][2] *= c1; o[i][3] *= c1;
        }

        // ---- repack P hi only (C-frag -> A-frag) ----
        uint32_t ph[4][4];
#pragma unroll
        for (int j = 0; j < 4; j++) {
            ph[j][0] = pack_h(sc[2 * j][0],     sc[2 * j][1]);
            ph[j][1] = pack_h(sc[2 * j][2],     sc[2 * j][3]);
            ph[j][2] = pack_h(sc[2 * j + 1][0], sc[2 * j + 1][1]);
            ph[j][3] = pack_h(sc[2 * j + 1][2], sc[2 * j + 1][3]);
        }

        // ---- O += P V (1-MMA, acc distance 8 across g) ----
#pragma unroll
        for (int j = 0; j < 4; j++) {
#pragma unroll
            for (int g = 0; g < 4; g++) {
                const uint32_t voff = (uint32_t)(j * 16) * AST + g * 32 + fragoff;
                uint32_t mh[4];
                ldmx4t(mh, uVhi + voff);
                uint32_t b0[2] = {mh[0], mh[1]}, b1[2] = {mh[2], mh[3]};
                mma_f16(o[2 * g + 0], ph[j], b0);
                mma_f16(o[2 * g + 1], ph[j], b1);
            }
        }
    }

    // ---- epilogue: write hi plane only ----
    const float inv0 = 1.f / l0;
    const float inv1 = 1.f / l1;
    const int r0 = qt * 128 + warp * 16 + (lane >> 2);
    const size_t base0 = ((size_t)b * Ss + r0) * Dd + headoff + (lane & 3) * 2;
    const size_t base1 = base0 + (size_t)8 * Dd;
#pragma unroll
    for (int nt = 0; nt < 8; nt++) {
        ((uint32_t*)ohi)[(base0 + nt * 8) / 2] = pack_h(o[nt][0] * inv0, o[nt][1] * inv0);
        ((uint32_t*)ohi)[(base1 + nt * 8) / 2] = pack_h(o[nt][2] * inv1, o[nt][3] * inv1);
    }
}

// ---------------------------------------------------------------------------
extern "C" void kernel_launch(void* const* d_in, const int* in_sizes, int n_in,
                              void* d_out, int out_size)
{
    (void)in_sizes; (void)n_in; (void)out_size;
    const float* x  = (const float*)d_in[0];
    const float* w1 = (const float*)d_in[1];
    const float* b1 = (const float*)d_in[2];
    const float* w2 = (const float*)d_in[3];
    const float* b2 = (const float*)d_in[4];
    float* out = (float*)d_out;

    __half *xhi, *xlo, *w1hi, *w1lo, *w2hi, *qhi, *qlo, *ahi;
    cudaGetSymbolAddress((void**)&xhi, g_xhi);
    cudaGetSymbolAddress((void**)&xlo, g_xlo);
    cudaGetSymbolAddress((void**)&w1hi, g_w1hi);
    cudaGetSymbolAddress((void**)&w1lo, g_w1lo);
    cudaGetSymbolAddress((void**)&w2hi, g_w2hi);
    cudaGetSymbolAddress((void**)&qhi, g_qkvhi);
    cudaGetSymbolAddress((void**)&qlo, g_qkvlo);
    cudaGetSymbolAddress((void**)&ahi, g_ahi);

    cudaFuncSetAttribute(gemm_hf<0>, cudaFuncAttributeMaxDynamicSharedMemorySize, GEMM_SMEM);
    cudaFuncSetAttribute(gemm_hf<1>, cudaFuncAttributeMaxDynamicSharedMemorySize, GEMM_SMEM);
    cudaFuncSetAttribute(flash2, cudaFuncAttributeMaxDynamicSharedMemorySize, ATTN_SMEM);

    // pre-convert
    split_f32<<<(MM * Dd / 2 + 255) / 256, 256>>>(x, xhi, xlo, MM * Dd / 2);
    transpose_split<<<dim3(N1 / 32, Dd / 64), 256>>>(w1, w1hi, w1lo, Dd, N1, 1);
    transpose_split<<<dim3(Dd / 32, Dd / 64), 256>>>(w2, w2hi, nullptr, Dd, Dd, 0);

    // 1) QKV projection (128x128 tiles, R11 shape):
    //    Q cols [0,1024):    3-MMA, hi out only (q-lo dead after flash cut)
    //    K cols [1024,2048): 3-MMA, hi+lo out
    //    V cols [2048,3072): 1-MMA, hi out
    gemm_hf<1><<<dim3(N1 / 128, MM / 128), 256, GEMM_SMEM>>>(
        xhi, xlo, w1hi, w1lo, b1, nullptr, qhi, qlo, MM, N1, Dd,
        /*n3lim=*/2 * Dd, /*alo=*/0, 2 * Dd, /*wlo=*/Dd, 2 * Dd);
    // 2) attention (QK 2-MMA, PV 1-MMA) -> a hi plane
    flash2<<<dim3(Ss / 128, Bb * Hh), 256, ATTN_SMEM>>>(qhi, qlo, ahi);
    // 3) output projection (1-MMA) -> fp32 out
    gemm_hf<0><<<dim3(Dd / 128, MM / 128), 256, GEMM_SMEM>>>(
        ahi, nullptr, w2hi, nullptr, b2, out, nullptr, nullptr, MM, Dd, Dd,
        /*n3lim=*/0, /*alo=*/0, 0, /*wlo=*/0, 0);
}

// round 15
// speedup vs baseline: 1.2821x; 1.0390x over previous
#include <cuda_runtime.h>
#include <cuda_fp16.h>
#include <cstdint>

// Problem constants
#define Bb 4
#define Ss 2048
#define Dd 1024
#define Hh 16
#define DHd 64
#define MM (Bb * Ss)          // 8192
#define N1 (3 * Dd)           // 3072

// ---------------- global scratch (fp16 hi/lo planes) ----------------
__device__ __half g_xhi[(size_t)MM * Dd];
__device__ __half g_xlo[(size_t)MM * Dd];
__device__ __half g_w1hi[(size_t)N1 * Dd];    // [n][k]
__device__ __half g_w1lo[(size_t)N1 * Dd];
__device__ __half g_w2hi[(size_t)Dd * Dd];    // [n][k]
__device__ __half g_qkvhi[(size_t)MM * N1];
__device__ __half g_qkvlo[(size_t)MM * N1];   // lo valid for K cols only
__device__ __half g_ahi[(size_t)MM * Dd];

// ---------------- helpers ----------------
__device__ __forceinline__ uint32_t s2u(const void* p) {
    uint32_t a;
    asm("{ .reg .u64 t; cvta.to.shared.u64 t, %1; cvt.u32.u64 %0, t; }" : "=r"(a) : "l"(p));
    return a;
}
__device__ __forceinline__ void cp16(uint32_t saddr, const void* gaddr) {
    asm volatile("cp.async.cg.shared.global [%0], [%1], 16;" :: "r"(saddr), "l"(gaddr));
}
#define CP_COMMIT() asm volatile("cp.async.commit_group;" ::: "memory")
#define CP_WAIT0()  asm volatile("cp.async.wait_group 0;" ::: "memory")

__device__ __forceinline__ void ldmx4(uint32_t* r, uint32_t addr) {
    asm volatile("ldmatrix.sync.aligned.m8n8.x4.shared.b16 {%0,%1,%2,%3}, [%4];"
        : "=r"(r[0]), "=r"(r[1]), "=r"(r[2]), "=r"(r[3]) : "r"(addr));
}
__device__ __forceinline__ void ldmx4t(uint32_t* r, uint32_t addr) {
    asm volatile("ldmatrix.sync.aligned.m8n8.x4.trans.shared.b16 {%0,%1,%2,%3}, [%4];"
        : "=r"(r[0]), "=r"(r[1]), "=r"(r[2]), "=r"(r[3]) : "r"(addr));
}
__device__ __forceinline__ void mma_f16(float* c, const uint32_t* a, const uint32_t* b) {
    asm volatile("mma.sync.aligned.m16n8k16.row.col.f32.f16.f16.f32 "
        "{%0,%1,%2,%3}, {%4,%5,%6,%7}, {%8,%9}, {%0,%1,%2,%3};"
        : "+f"(c[0]), "+f"(c[1]), "+f"(c[2]), "+f"(c[3])
        : "r"(a[0]), "r"(a[1]), "r"(a[2]), "r"(a[3]), "r"(b[0]), "r"(b[1]));
}
// fp32 pair -> packed fp16 hi pair + fp16 lo pair (hi = rn(f), lo = rn(f - hi))
__device__ __forceinline__ void cvt_packh(float f0, float f1, uint32_t& hi, uint32_t& lo) {
    __half h0 = __float2half_rn(f0);
    __half h1 = __float2half_rn(f1);
    __half l0 = __float2half_rn(f0 - __half2float(h0));
    __half l1 = __float2half_rn(f1 - __half2float(h1));
    hi = ((uint32_t)__half_as_ushort(h1) << 16) | (uint32_t)__half_as_ushort(h0);
    lo = ((uint32_t)__half_as_ushort(l1) << 16) | (uint32_t)__half_as_ushort(l0);
}
__device__ __forceinline__ uint32_t pack_h(float f0, float f1) {
    __half h0 = __float2half_rn(f0);
    __half h1 = __float2half_rn(f1);
    return ((uint32_t)__half_as_ushort(h1) << 16) | (uint32_t)__half_as_ushort(h0);
}

// ---------------------------------------------------------------------------
// Fused pre-convert: one launch covering
//   [0, NXB)            : x fp32 -> xhi/xlo planes (elementwise)
//   [NXB, NXB+1536)     : w1 [K][N] -> [N][K] hi+lo transpose tiles
//   [NXB+1536, +512)    : w2 [K][N] -> [N][K] hi-only transpose tiles
// ---------------------------------------------------------------------------
#define NXB (MM * Dd / 2 / 256)      // 16384 blocks for x split
#define NW1B ((N1 / 32) * (Dd / 64)) // 1536
#define NW2B ((Dd / 32) * (Dd / 64)) // 512

__global__ void __launch_bounds__(256) preconvert(
    const float* __restrict__ x, __half* __restrict__ xhi, __half* __restrict__ xlo,
    const float* __restrict__ w1, __half* __restrict__ w1hi, __half* __restrict__ w1lo,
    const float* __restrict__ w2, __half* __restrict__ w2hi)
{
    __shared__ float sm[64][33];
    const int tid = threadIdx.x;
    const int bx = blockIdx.x;

    if (bx < NXB) {
        // ---- x split ----
        const int i = bx * 256 + tid;
        float2 v = *(const float2*)(x + 2 * i);
        uint32_t h, l;
        cvt_packh(v.x, v.y, h, l);
        ((uint32_t*)xhi)[i] = h;
        ((uint32_t*)xlo)[i] = l;
        return;
    }

    // ---- weight transpose+split ----
    const float* W;
    __half* Whi;
    __half* Wlo;
    int Nw, n0, k0, write_lo;
    if (bx < NXB + NW1B) {
        const int id = bx - NXB;
        W = w1; Whi = w1hi; Wlo = w1lo; Nw = N1; write_lo = 1;
        n0 = (id % (N1 / 32)) * 32;
        k0 = (id / (N1 / 32)) * 64;
    } else {
        const int id = bx - NXB - NW1B;
        W = w2; Whi = w2hi; Wlo = nullptr; Nw = Dd; write_lo = 0;
        n0 = (id % (Dd / 32)) * 32;
        k0 = (id / (Dd / 32)) * 64;
    }
#pragma unroll
    for (int p = 0; p < 8; p++) {
        const int k = p * 8 + (tid >> 5);
        const int n = tid & 31;
        sm[k][n] = W[(size_t)(k0 + k) * Nw + n0 + n];
    }
    __syncthreads();
#pragma unroll
    for (int p = 0; p < 4; p++) {
        const int n = p * 8 + (tid >> 5);
        const int kp = tid & 31;
        uint32_t h, l;
        cvt_packh(sm[2 * kp][n], sm[2 * kp + 1][n], h, l);
        const size_t idx = ((size_t)(n0 + n) * Dd + k0) / 2 + kp;
        ((uint32_t*)Whi)[idx] = h;
        if (write_lo) ((uint32_t*)Wlo)[idx] = l;
    }
}

// ---------------------------------------------------------------------------
// GEMM from fp16 planes (128x128 tile, BK=32, 2 CTAs/SM).
// Passes: ah·bh always; ah·bl when col0 < n3lim; al·bh in [alo_lo, alo_hi).
// EPI: 0 -> fp32 C (2D grid), 1 -> fp16 hi plane (+lo in [wlo_lo, wlo_hi)),
//   launched with a 1D grid using heavy-first tile ordering (Q/K tiles first,
//   cheap V tiles last -> good tail backfill).
// ---------------------------------------------------------------------------
#define GST 80
#define GTILE (128 * GST)
#define GSTAGE (4 * GTILE)
#define GEMM_SMEM (2 * GSTAGE)

template<int EPI>
__global__ void __launch_bounds__(256, 2) gemm_hf(
    const __half* __restrict__ Ahi, const __half* __restrict__ Alo,
    const __half* __restrict__ Bhi, const __half* __restrict__ Blo,
    const float* __restrict__ bias, float* __restrict__ Cf,
    __half* __restrict__ Chi, __half* __restrict__ Clo,
    int M, int N, int K, int n3lim, int alo_lo, int alo_hi,
    int wlo_lo, int wlo_hi)
{
    extern __shared__ char smem[];
    const int tid = threadIdx.x;
    const int lane = tid & 31;
    const int warp = tid >> 5;
    const int wm = warp >> 2;
    const int wn = warp & 3;

    // Tile mapping: 2D grid -> direct; 1D grid (GEMM1) -> heavy-first order:
    // ids [0,1024) cover Q/K columns (x 0..15), ids [1024,1536) cover V (x 16..23).
    int bx, by;
    if (gridDim.y == 1) {
        const int id = blockIdx.x;
        if (id < 1024) { bx = id & 15; by = id >> 4; }
        else { const int v = id - 1024; bx = 16 + (v & 7); by = v >> 3; }
    } else {
        bx = blockIdx.x; by = blockIdx.y;
    }
    const int row0 = by * 128;
    const int col0 = bx * 128;
    const bool use3 = (col0 < n3lim);
    const bool ualo = (col0 >= alo_lo) && (col0 < alo_hi);

    const int lrow = tid >> 1;
    const int lq = (tid & 1) * 2;

    auto issue = [&](int kc, int s) {
        char* stg = smem + s * GSTAGE;
        const uint32_t sA = s2u(stg) + (uint32_t)lrow * GST + lq * 16;
        const size_t gOffA = (size_t)(row0 + lrow) * K + kc * 32 + lq * 8;
        cp16(sA, Ahi + gOffA);
        cp16(sA + 16, Ahi + gOffA + 8);
        if (ualo) {
            cp16(sA + GTILE, Alo + gOffA);
            cp16(sA + GTILE + 16, Alo + gOffA + 8);
        }
        const size_t gOffB = (size_t)(col0 + lrow) * K + kc * 32 + lq * 8;
        cp16(sA + 2 * GTILE, Bhi + gOffB);
        cp16(sA + 2 * GTILE + 16, Bhi + gOffB + 8);
        if (use3) {
            cp16(sA + 3 * GTILE, Blo + gOffB);
            cp16(sA + 3 * GTILE + 16, Blo + gOffB + 8);
        }
    };

    float acc[4][4][4];
#pragma unroll
    for (int i = 0; i < 4; i++)
#pragma unroll
        for (int j = 0; j < 4; j++)
#pragma unroll
            for (int e = 0; e < 4; e++) acc[i][j][e] = 0.f;

    const uint32_t fragoff = (uint32_t)(lane & 15) * GST + (uint32_t)(lane >> 4) * 16;

    issue(0, 0);
    CP_COMMIT();

    const int nch = K / 32;
    for (int kc = 0; kc < nch; kc++) {
        const int s = kc & 1;
        CP_WAIT0();
        __syncthreads();
        if (kc + 1 < nch) {
            issue(kc + 1, s ^ 1);
            CP_COMMIT();
        }
        char* stg = smem + s * GSTAGE;
        const uint32_t uAhi = s2u(stg);
        const uint32_t uAlo = uAhi + GTILE;
        const uint32_t uBhi = uAhi + 2 * GTILE;
        const uint32_t uBlo = uAhi + 3 * GTILE;

#pragma unroll
        for (int ks = 0; ks < 2; ks++) {
            const uint32_t kb = (uint32_t)ks * 32;
            uint32_t bh[4][2], bl[4][2];
#pragma unroll
            for (int ntp = 0; ntp < 2; ntp++) {
                const uint32_t boff = (uint32_t)(wn * 32 + ntp * 16) * GST + kb + fragoff;
                uint32_t m[4];
                ldmx4(m, uBhi + boff);
                bh[ntp * 2 + 0][0] = m[0]; bh[ntp * 2 + 1][0] = m[1];
                bh[ntp * 2 + 0][1] = m[2]; bh[ntp * 2 + 1][1] = m[3];
                if (use3) {
                    ldmx4(m, uBlo + boff);
                    bl[ntp * 2 + 0][0] = m[0]; bl[ntp * 2 + 1][0] = m[1];
                    bl[ntp * 2 + 0][1] = m[2]; bl[ntp * 2 + 1][1] = m[3];
                }
            }
            uint32_t ah[4][4];
#pragma unroll
            for (int mt = 0; mt < 4; mt++) {
                const uint32_t aoff = (uint32_t)(wm * 64 + mt * 16) * GST + kb + fragoff;
                ldmx4(ah[mt], uAhi + aoff);
            }
            // PASS 1: ah·bh
#pragma unroll
            for (int mt = 0; mt < 4; mt++)
#pragma unroll
                for (int nt = 0; nt < 4; nt++)
                    mma_f16(acc[mt][nt], ah[mt], bh[nt]);
            // PASS 2: ah·bl
            if (use3) {
#pragma unroll
                for (int mt = 0; mt < 4; mt++)
#pragma unroll
                    for (int nt = 0; nt < 4; nt++)
                        mma_f16(acc[mt][nt], ah[mt], bl[nt]);
            }
            // PASS 3: al·bh
            if (ualo) {
#pragma unroll
                for (int mt = 0; mt < 4; mt++) {
                    const uint32_t aoff = (uint32_t)(wm * 64 + mt * 16) * GST + kb + fragoff;
                    uint32_t al[4];
                    ldmx4(al, uAlo + aoff);
#pragma unroll
                    for (int nt = 0; nt < 4; nt++)
                        mma_f16(acc[mt][nt], al, bh[nt]);
                }
            }
        }
    }

    // epilogue
    const bool wlo = (col0 >= wlo_lo) && (col0 < wlo_hi);
#pragma unroll
    for (int mt = 0; mt < 4; mt++) {
        const int r = row0 + wm * 64 + mt * 16 + (lane >> 2);
#pragma unroll
        for (int nt = 0; nt < 4; nt++) {
            const int c = col0 + wn * 32 + nt * 8 + (lane & 3) * 2;
            const float bx2 = bias[c];
            const float by2 = bias[c + 1];
            const float f0 = acc[mt][nt][0] + bx2;
            const float f1 = acc[mt][nt][1] + by2;
            const float f2 = acc[mt][nt][2] + bx2;
            const float f3 = acc[mt][nt][3] + by2;
            if (EPI == 0) {
                *(float2*)(Cf + (size_t)r * N + c) = make_float2(f0, f1);
                *(float2*)(Cf + (size_t)(r + 8) * N + c) = make_float2(f2, f3);
            } else {
                uint32_t h0, l0, h1, l1;
                cvt_packh(f0, f1, h0, l0);
                cvt_packh(f2, f3, h1, l1);
                const size_t i0 = ((size_t)r * N + c) / 2;
                const size_t i1 = ((size_t)(r + 8) * N + c) / 2;
                ((uint32_t*)Chi)[i0] = h0;
                ((uint32_t*)Chi)[i1] = h1;
                if (wlo) {
                    ((uint32_t*)Clo)[i0] = l0;
                    ((uint32_t*)Clo)[i1] = l1;
                }
            }
        }
    }
}

// ---------------------------------------------------------------------------
// Flash attention from fp16 qkv planes (identical to R14).
// QK: 2-MMA (qh·Khi + qh·Klo). PV: 1-MMA. Output: hi plane only.
// ---------------------------------------------------------------------------
#define AST 144
#define ATL (64 * AST)
#define ASTG (3 * ATL)              // Khi,Klo,Vhi = 27648
#define ATTN_SMEM (2 * ASTG)        // 55296 (Q-hi staging overlaps stage1)

__global__ void __launch_bounds__(256) flash2(
    const __half* __restrict__ qhi, const __half* __restrict__ qlo,
    __half* __restrict__ ohi)
{
    extern __shared__ char smem[];
    const int tid = threadIdx.x;
    const int lane = tid & 31;
    const int warp = tid >> 5;
    const int qt = blockIdx.x;
    const int bh = blockIdx.y;
    const int b = bh >> 4;
    const int h = bh & 15;

    const uint32_t sb = s2u(smem);
    const uint32_t fragoff = (uint32_t)(lane & 15) * AST + (uint32_t)(lane >> 4) * 16;
    const size_t headoff = (size_t)h * DHd;

    const int krow = tid >> 2;
    const int kcc = (tid & 3) * 2;
    auto issueKV = [&](int kb, int s) {
        const uint32_t sB = sb + s * ASTG + (uint32_t)krow * AST + kcc * 16;
        const size_t g = ((size_t)b * Ss + kb * 64 + krow) * N1 + headoff + kcc * 8;
        cp16(sB,                 qhi + g + Dd);       // K hi
        cp16(sB + 16,            qhi + g + Dd + 8);
        cp16(sB + ATL,           qlo + g + Dd);       // K lo
        cp16(sB + ATL + 16,      qlo + g + Dd + 8);
        cp16(sB + 2 * ATL,       qhi + g + 2 * Dd);   // V hi
        cp16(sB + 2 * ATL + 16,  qhi + g + 2 * Dd + 8);
    };

    issueKV(0, 0);
    CP_COMMIT();
    {
        const int qrow = tid >> 1;
        const int q4 = (tid & 1) * 4;
        const uint32_t sQh = sb + ASTG + (uint32_t)qrow * AST + q4 * 16;
        const size_t g = ((size_t)b * Ss + qt * 128 + qrow) * N1 + headoff + q4 * 8;
#pragma unroll
        for (int i = 0; i < 4; i++)
            cp16(sQh + i * 16, qhi + g + i * 8);
    }
    CP_COMMIT();
    CP_WAIT0();
    __syncthreads();

    uint32_t qh[4][4];
    {
        const uint32_t uQh = sb + ASTG;
#pragma unroll
        for (int j = 0; j < 4; j++) {
            const uint32_t aoff = (uint32_t)(warp * 16) * AST + j * 32 + fragoff;
            ldmx4(qh[j], uQh + aoff);
        }
    }

    float o[8][4];
    float m0 = -1e30f, m1 = -1e30f, l0 = 0.f, l1 = 0.f;
#pragma unroll
    for (int i = 0; i < 8; i++)
#pragma unroll
        for (int e = 0; e < 4; e++) o[i][e] = 0.f;

    for (int kb = 0; kb < Ss / 64; kb++) {
        const int s = kb & 1;
        if (kb > 0) CP_WAIT0();
        __syncthreads();
        if (kb + 1 < Ss / 64) {
            issueKV(kb + 1, s ^ 1);
            CP_COMMIT();
        }
        const uint32_t uKhi = sb + s * ASTG;
        const uint32_t uKlo = uKhi + ATL;
        const uint32_t uVhi = uKhi + 2 * ATL;

        float sc[8][4];
#pragma unroll
        for (int i = 0; i < 8; i++)
#pragma unroll
            for (int e = 0; e < 4; e++) sc[i][e] = 0.f;

#pragma unroll
        for (int j = 0; j < 4; j++) {
#pragma unroll
            for (int g = 0; g < 4; g++) {
                const uint32_t boff = (uint32_t)(g * 16) * AST + j * 32 + fragoff;
                uint32_t mh[4];
                ldmx4(mh, uKhi + boff);
                uint32_t b0[2] = {mh[0], mh[2]}, b1[2] = {mh[1], mh[3]};
                mma_f16(sc[2 * g + 0], qh[j], b0);
                mma_f16(sc[2 * g + 1], qh[j], b1);
            }
#pragma unroll
            for (int g = 0; g < 4; g++) {
                const uint32_t boff = (uint32_t)(g * 16) * AST + j * 32 + fragoff;
                uint32_t ml[4];
                ldmx4(ml, uKlo + boff);
                uint32_t b0[2] = {ml[0], ml[2]}, b1[2] = {ml[1], ml[3]};
                mma_f16(sc[2 * g + 0], qh[j], b0);
                mma_f16(sc[2 * g + 1], qh[j], b1);
            }
        }

        // ---- online softmax ----
        float mx0 = -1e30f, mx1 = -1e30f;
#pragma unroll
        for (int i = 0; i < 8; i++) {
            mx0 = fmaxf(mx0, fmaxf(sc[i][0], sc[i][1]));
            mx1 = fmaxf(mx1, fmaxf(sc[i][2], sc[i][3]));
        }
        mx0 = fmaxf(mx0, __shfl_xor_sync(0xffffffffu, mx0, 1));
        mx0 = fmaxf(mx0, __shfl_xor_sync(0xffffffffu, mx0, 2));
        mx1 = fmaxf(mx1, __shfl_xor_sync(0xffffffffu, mx1, 1));
        mx1 = fmaxf(mx1, __shfl_xor_sync(0xffffffffu, mx1, 2));
        const float mn0 = fmaxf(m0, mx0);
        const float mn1 = fmaxf(m1, mx1);
        const float c0 = __expf(m0 - mn0);
        const float c1 = __expf(m1 - mn1);
        float rs0 = 0.f, rs1 = 0.f;
#pragma unroll
        for (int i = 0; i < 8; i++) {
            sc[i][0] = __expf(sc[i][0] - mn0);
            sc[i][1] = __expf(sc[i][1] - mn0);
            sc[i][2] = __expf(sc[i][2] - mn1);
            sc[i][3] = __expf(sc[i][3] - mn1);
            rs0 += sc[i][0] + sc[i][1];
            rs1 += sc[i][2] + sc[i][3];
        }
        rs0 += __shfl_xor_sync(0xffffffffu, rs0, 1);
        rs0 += __shfl_xor_sync(0xffffffffu, rs0, 2);
        rs1 += __shfl_xor_sync(0xffffffffu, rs1, 1);
        rs1 += __shfl_xor_sync(0xffffffffu, rs1, 2);
        l0 = l0 * c0 + rs0;
        l1 = l1 * c1 + rs1;
        m0 = mn0;
        m1 = mn1;
#pragma unroll
        for (int i = 0; i < 8; i++) {
            o[i][0] *= c0; o[i][1] *= c0;
            o[i][2] *= c1; o[i][3] *= c1;
        }

        uint32_t ph[4][4];
#pragma unroll
        for (int j = 0; j < 4; j++) {
            ph[j][0] = pack_h(sc[2 * j][0],     sc[2 * j][1]);
            ph[j][1] = pack_h(sc[2 * j][2],     sc[2 * j][3]);
            ph[j][2] = pack_h(sc[2 * j + 1][0], sc[2 * j + 1][1]);
            ph[j][3] = pack_h(sc[2 * j + 1][2], sc[2 * j + 1][3]);
        }

#pragma unroll
        for (int j = 0; j < 4; j++) {
#pragma unroll
            for (int g = 0; g < 4; g++) {
                const uint32_t voff = (uint32_t)(j * 16) * AST + g * 32 + fragoff;
                uint32_t mh[4];
                ldmx4t(mh, uVhi + voff);
                uint32_t b0[2] = {mh[0], mh[1]}, b1[2] = {mh[2], mh[3]};
                mma_f16(o[2 * g + 0], ph[j], b0);
                mma_f16(o[2 * g + 1], ph[j], b1);
            }
        }
    }

    const float inv0 = 1.f / l0;
    const float inv1 = 1.f / l1;
    const int r0 = qt * 128 + warp * 16 + (lane >> 2);
    const size_t base0 = ((size_t)b * Ss + r0) * Dd + headoff + (lane & 3) * 2;
    const size_t base1 = base0 + (size_t)8 * Dd;
#pragma unroll
    for (int nt = 0; nt < 8; nt++) {
        ((uint32_t*)ohi)[(base0 + nt * 8) / 2] = pack_h(o[nt][0] * inv0, o[nt][1] * inv0);
        ((uint32_t*)ohi)[(base1 + nt * 8) / 2] = pack_h(o[nt][2] * inv1, o[nt][3] * inv1);
    }
}

// ---------------------------------------------------------------------------
extern "C" void kernel_launch(void* const* d_in, const int* in_sizes, int n_in,
                              void* d_out, int out_size)
{
    (void)in_sizes; (void)n_in; (void)out_size;
    const float* x  = (const float*)d_in[0];
    const float* w1 = (const float*)d_in[1];
    const float* b1 = (const float*)d_in[2];
    const float* w2 = (const float*)d_in[3];
    const float* b2 = (const float*)d_in[4];
    float* out = (float*)d_out;

    __half *xhi, *xlo, *w1hi, *w1lo, *w2hi, *qhi, *qlo, *ahi;
    cudaGetSymbolAddress((void**)&xhi, g_xhi);
    cudaGetSymbolAddress((void**)&xlo, g_xlo);
    cudaGetSymbolAddress((void**)&w1hi, g_w1hi);
    cudaGetSymbolAddress((void**)&w1lo, g_w1lo);
    cudaGetSymbolAddress((void**)&w2hi, g_w2hi);
    cudaGetSymbolAddress((void**)&qhi, g_qkvhi);
    cudaGetSymbolAddress((void**)&qlo, g_qkvlo);
    cudaGetSymbolAddress((void**)&ahi, g_ahi);

    cudaFuncSetAttribute(gemm_hf<0>, cudaFuncAttributeMaxDynamicSharedMemorySize, GEMM_SMEM);
    cudaFuncSetAttribute(gemm_hf<1>, cudaFuncAttributeMaxDynamicSharedMemorySize, GEMM_SMEM);
    cudaFuncSetAttribute(flash2, cudaFuncAttributeMaxDynamicSharedMemorySize, ATTN_SMEM);

    // 0) fused pre-convert (x split + w1/w2 transpose in one launch)
    preconvert<<<NXB + NW1B + NW2B, 256>>>(x, xhi, xlo, w1, w1hi, w1lo, w2, w2hi);

    // 1) QKV projection, 1D grid with heavy-first tile ordering:
    //    Q cols [0,1024):    3-MMA, hi out only
    //    K cols [1024,2048): 3-MMA, hi+lo out
    //    V cols [2048,3072): 1-MMA, hi out  (these cheap tiles launch last)
    gemm_hf<1><<<dim3(N1 / 128 * (MM / 128), 1), 256, GEMM_SMEM>>>(
        xhi, xlo, w1hi, w1lo, b1, nullptr, qhi, qlo, MM, N1, Dd,
        /*n3lim=*/2 * Dd, /*alo=*/0, 2 * Dd, /*wlo=*/Dd, 2 * Dd);
    // 2) attention (QK 2-MMA, PV 1-MMA) -> a hi plane
    flash2<<<dim3(Ss / 128, Bb * Hh), 256, ATTN_SMEM>>>(qhi, qlo, ahi);
    // 3) output projection (1-MMA) -> fp32 out (2D grid)
    gemm_hf<0><<<dim3(Dd / 128, MM / 128), 256, GEMM_SMEM>>>(
        ahi, nullptr, w2hi, nullptr, b2, out, nullptr, nullptr, MM, Dd, Dd,
        /*n3lim=*/0, /*alo=*/0, 0, /*wlo=*/0, 0);
}

// round 16
// speedup vs baseline: 1.2927x; 1.0083x over previous
#include <cuda_runtime.h>
#include <cuda_fp16.h>
#include <cstdint>

// Problem constants
#define Bb 4
#define Ss 2048
#define Dd 1024
#define Hh 16
#define DHd 64
#define MM (Bb * Ss)          // 8192
#define N1 (3 * Dd)           // 3072

// ---------------- global scratch (fp16 hi/lo planes) ----------------
__device__ __half g_xhi[(size_t)MM * Dd];
__device__ __half g_xlo[(size_t)MM * Dd];
__device__ __half g_w1hi[(size_t)N1 * Dd];    // [n][k]
__device__ __half g_w1lo[(size_t)N1 * Dd];
__device__ __half g_w2hi[(size_t)Dd * Dd];    // [n][k]
__device__ __half g_qkvhi[(size_t)MM * N1];
__device__ __half g_qkvlo[(size_t)MM * N1];   // lo valid for K cols only
__device__ __half g_ahi[(size_t)MM * Dd];

// ---------------- helpers ----------------
__device__ __forceinline__ uint32_t s2u(const void* p) {
    uint32_t a;
    asm("{ .reg .u64 t; cvta.to.shared.u64 t, %1; cvt.u32.u64 %0, t; }" : "=r"(a) : "l"(p));
    return a;
}
__device__ __forceinline__ void cp16(uint32_t saddr, const void* gaddr) {
    asm volatile("cp.async.cg.shared.global [%0], [%1], 16;" :: "r"(saddr), "l"(gaddr));
}
#define CP_COMMIT() asm volatile("cp.async.commit_group;" ::: "memory")
#define CP_WAIT0()  asm volatile("cp.async.wait_group 0;" ::: "memory")
#define CP_WAIT2()  asm volatile("cp.async.wait_group 2;" ::: "memory")

__device__ __forceinline__ void ldmx4(uint32_t* r, uint32_t addr) {
    asm volatile("ldmatrix.sync.aligned.m8n8.x4.shared.b16 {%0,%1,%2,%3}, [%4];"
        : "=r"(r[0]), "=r"(r[1]), "=r"(r[2]), "=r"(r[3]) : "r"(addr));
}
__device__ __forceinline__ void ldmx4t(uint32_t* r, uint32_t addr) {
    asm volatile("ldmatrix.sync.aligned.m8n8.x4.trans.shared.b16 {%0,%1,%2,%3}, [%4];"
        : "=r"(r[0]), "=r"(r[1]), "=r"(r[2]), "=r"(r[3]) : "r"(addr));
}
__device__ __forceinline__ void mma_f16(float* c, const uint32_t* a, const uint32_t* b) {
    asm volatile("mma.sync.aligned.m16n8k16.row.col.f32.f16.f16.f32 "
        "{%0,%1,%2,%3}, {%4,%5,%6,%7}, {%8,%9}, {%0,%1,%2,%3};"
        : "+f"(c[0]), "+f"(c[1]), "+f"(c[2]), "+f"(c[3])
        : "r"(a[0]), "r"(a[1]), "r"(a[2]), "r"(a[3]), "r"(b[0]), "r"(b[1]));
}
// fp32 pair -> packed fp16 hi pair + fp16 lo pair (hi = rn(f), lo = rn(f - hi))
__device__ __forceinline__ void cvt_packh(float f0, float f1, uint32_t& hi, uint32_t& lo) {
    __half h0 = __float2half_rn(f0);
    __half h1 = __float2half_rn(f1);
    __half l0 = __float2half_rn(f0 - __half2float(h0));
    __half l1 = __float2half_rn(f1 - __half2float(h1));
    hi = ((uint32_t)__half_as_ushort(h1) << 16) | (uint32_t)__half_as_ushort(h0);
    lo = ((uint32_t)__half_as_ushort(l1) << 16) | (uint32_t)__half_as_ushort(l0);
}
__device__ __forceinline__ uint32_t pack_h(float f0, float f1) {
    __half h0 = __float2half_rn(f0);
    __half h1 = __float2half_rn(f1);
    return ((uint32_t)__half_as_ushort(h1) << 16) | (uint32_t)__half_as_ushort(h0);
}

// ---------------------------------------------------------------------------
// Fused pre-convert (unchanged from R15).
// ---------------------------------------------------------------------------
#define NXB (MM * Dd / 2 / 256)      // 16384 blocks for x split
#define NW1B ((N1 / 32) * (Dd / 64)) // 1536
#define NW2B ((Dd / 32) * (Dd / 64)) // 512

__global__ void __launch_bounds__(256) preconvert(
    const float* __restrict__ x, __half* __restrict__ xhi, __half* __restrict__ xlo,
    const float* __restrict__ w1, __half* __restrict__ w1hi, __half* __restrict__ w1lo,
    const float* __restrict__ w2, __half* __restrict__ w2hi)
{
    __shared__ float sm[64][33];
    const int tid = threadIdx.x;
    const int bx = blockIdx.x;

    if (bx < NXB) {
        const int i = bx * 256 + tid;
        float2 v = *(const float2*)(x + 2 * i);
        uint32_t h, l;
        cvt_packh(v.x, v.y, h, l);
        ((uint32_t*)xhi)[i] = h;
        ((uint32_t*)xlo)[i] = l;
        return;
    }

    const float* W;
    __half* Whi;
    __half* Wlo;
    int Nw, n0, k0, write_lo;
    if (bx < NXB + NW1B) {
        const int id = bx - NXB;
        W = w1; Whi = w1hi; Wlo = w1lo; Nw = N1; write_lo = 1;
        n0 = (id % (N1 / 32)) * 32;
        k0 = (id / (N1 / 32)) * 64;
    } else {
        const int id = bx - NXB - NW1B;
        W = w2; Whi = w2hi; Wlo = nullptr; Nw = Dd; write_lo = 0;
        n0 = (id % (Dd / 32)) * 32;
        k0 = (id / (Dd / 32)) * 64;
    }
#pragma unroll
    for (int p = 0; p < 8; p++) {
        const int k = p * 8 + (tid >> 5);
        const int n = tid & 31;
        sm[k][n] = W[(size_t)(k0 + k) * Nw + n0 + n];
    }
    __syncthreads();
#pragma unroll
    for (int p = 0; p < 4; p++) {
        const int n = p * 8 + (tid >> 5);
        const int kp = tid & 31;
        uint32_t h, l;
        cvt_packh(sm[2 * kp][n], sm[2 * kp + 1][n], h, l);
        const size_t idx = ((size_t)(n0 + n) * Dd + k0) / 2 + kp;
        ((uint32_t*)Whi)[idx] = h;
        if (write_lo) ((uint32_t*)Wlo)[idx] = l;
    }
}

// ---------------------------------------------------------------------------
// GEMM1 (unchanged from R15): fp16 planes, 128x128 tile, BK=32, 2-stage,
// heavy-first 1D grid, range-configured passes, fp16 epilogue.
// ---------------------------------------------------------------------------
#define GST 80
#define GTILE (128 * GST)
#define GSTAGE (4 * GTILE)
#define GEMM_SMEM (2 * GSTAGE)

__global__ void __launch_bounds__(256, 2) gemm_hf1(
    const __half* __restrict__ Ahi, const __half* __restrict__ Alo,
    const __half* __restrict__ Bhi, const __half* __restrict__ Blo,
    const float* __restrict__ bias,
    __half* __restrict__ Chi, __half* __restrict__ Clo,
    int M, int N, int K, int n3lim, int alo_lo, int alo_hi,
    int wlo_lo, int wlo_hi)
{
    extern __shared__ char smem[];
    const int tid = threadIdx.x;
    const int lane = tid & 31;
    const int warp = tid >> 5;
    const int wm = warp >> 2;
    const int wn = warp & 3;

    // heavy-first 1D mapping: ids [0,1024) -> Q/K cols (x 0..15),
    // ids [1024,1536) -> V cols (x 16..23)
    int bx, by;
    {
        const int id = blockIdx.x;
        if (id < 1024) { bx = id & 15; by = id >> 4; }
        else { const int v = id - 1024; bx = 16 + (v & 7); by = v >> 3; }
    }
    const int row0 = by * 128;
    const int col0 = bx * 128;
    const bool use3 = (col0 < n3lim);
    const bool ualo = (col0 >= alo_lo) && (col0 < alo_hi);

    const int lrow = tid >> 1;
    const int lq = (tid & 1) * 2;

    auto issue = [&](int kc, int s) {
        char* stg = smem + s * GSTAGE;
        const uint32_t sA = s2u(stg) + (uint32_t)lrow * GST + lq * 16;
        const size_t gOffA = (size_t)(row0 + lrow) * K + kc * 32 + lq * 8;
        cp16(sA, Ahi + gOffA);
        cp16(sA + 16, Ahi + gOffA + 8);
        if (ualo) {
            cp16(sA + GTILE, Alo + gOffA);
            cp16(sA + GTILE + 16, Alo + gOffA + 8);
        }
        const size_t gOffB = (size_t)(col0 + lrow) * K + kc * 32 + lq * 8;
        cp16(sA + 2 * GTILE, Bhi + gOffB);
        cp16(sA + 2 * GTILE + 16, Bhi + gOffB + 8);
        if (use3) {
            cp16(sA + 3 * GTILE, Blo + gOffB);
            cp16(sA + 3 * GTILE + 16, Blo + gOffB + 8);
        }
    };

    float acc[4][4][4];
#pragma unroll
    for (int i = 0; i < 4; i++)
#pragma unroll
        for (int j = 0; j < 4; j++)
#pragma unroll
            for (int e = 0; e < 4; e++) acc[i][j][e] = 0.f;

    const uint32_t fragoff = (uint32_t)(lane & 15) * GST + (uint32_t)(lane >> 4) * 16;

    issue(0, 0);
    CP_COMMIT();

    const int nch = K / 32;
    for (int kc = 0; kc < nch; kc++) {
        const int s = kc & 1;
        CP_WAIT0();
        __syncthreads();
        if (kc + 1 < nch) {
            issue(kc + 1, s ^ 1);
            CP_COMMIT();
        }
        char* stg = smem + s * GSTAGE;
        const uint32_t uAhi = s2u(stg);
        const uint32_t uAlo = uAhi + GTILE;
        const uint32_t uBhi = uAhi + 2 * GTILE;
        const uint32_t uBlo = uAhi + 3 * GTILE;

#pragma unroll
        for (int ks = 0; ks < 2; ks++) {
            const uint32_t kb = (uint32_t)ks * 32;
            uint32_t bh[4][2], bl[4][2];
#pragma unroll
            for (int ntp = 0; ntp < 2; ntp++) {
                const uint32_t boff = (uint32_t)(wn * 32 + ntp * 16) * GST + kb + fragoff;
                uint32_t m[4];
                ldmx4(m, uBhi + boff);
                bh[ntp * 2 + 0][0] = m[0]; bh[ntp * 2 + 1][0] = m[1];
                bh[ntp * 2 + 0][1] = m[2]; bh[ntp * 2 + 1][1] = m[3];
                if (use3) {
                    ldmx4(m, uBlo + boff);
                    bl[ntp * 2 + 0][0] = m[0]; bl[ntp * 2 + 1][0] = m[1];
                    bl[ntp * 2 + 0][1] = m[2]; bl[ntp * 2 + 1][1] = m[3];
                }
            }
            uint32_t ah[4][4];
#pragma unroll
            for (int mt = 0; mt < 4; mt++) {
                const uint32_t aoff = (uint32_t)(wm * 64 + mt * 16) * GST + kb + fragoff;
                ldmx4(ah[mt], uAhi + aoff);
            }
#pragma unroll
            for (int mt = 0; mt < 4; mt++)
#pragma unroll
                for (int nt = 0; nt < 4; nt++)
                    mma_f16(acc[mt][nt], ah[mt], bh[nt]);
            if (use3) {
#pragma unroll
                for (int mt = 0; mt < 4; mt++)
#pragma unroll
                    for (int nt = 0; nt < 4; nt++)
                        mma_f16(acc[mt][nt], ah[mt], bl[nt]);
            }
            if (ualo) {
#pragma unroll
                for (int mt = 0; mt < 4; mt++) {
                    const uint32_t aoff = (uint32_t)(wm * 64 + mt * 16) * GST + kb + fragoff;
                    uint32_t al[4];
                    ldmx4(al, uAlo + aoff);
#pragma unroll
                    for (int nt = 0; nt < 4; nt++)
                        mma_f16(acc[mt][nt], al, bh[nt]);
                }
            }
        }
    }

    const bool wlo = (col0 >= wlo_lo) && (col0 < wlo_hi);
#pragma unroll
    for (int mt = 0; mt < 4; mt++) {
        const int r = row0 + wm * 64 + mt * 16 + (lane >> 2);
#pragma unroll
        for (int nt = 0; nt < 4; nt++) {
            const int c = col0 + wn * 32 + nt * 8 + (lane & 3) * 2;
            const float bx2 = bias[c];
            const float by2 = bias[c + 1];
            const float f0 = acc[mt][nt][0] + bx2;
            const float f1 = acc[mt][nt][1] + by2;
            const float f2 = acc[mt][nt][2] + bx2;
            const float f3 = acc[mt][nt][3] + by2;
            uint32_t h0, l0, h1, l1;
            cvt_packh(f0, f1, h0, l0);
            cvt_packh(f2, f3, h1, l1);
            const size_t i0 = ((size_t)r * N + c) / 2;
            const size_t i1 = ((size_t)(r + 8) * N + c) / 2;
            ((uint32_t*)Chi)[i0] = h0;
            ((uint32_t*)Chi)[i1] = h1;
            if (wlo) {
                ((uint32_t*)Clo)[i0] = l0;
                ((uint32_t*)Clo)[i1] = l1;
            }
        }
    }
}

// ---------------------------------------------------------------------------
// GEMM2 lite: C = A @ B^T + bias, hi planes only (1-MMA), fp32 out.
// 128x128 tile, BK=32, 4-STAGE cp.async ring (wait_group 2) — hides load
// latency that the 2-stage version exposed (GEMM2 measured 54 cyc/MMA).
// Same MMA order as before -> bit-identical results.
// ---------------------------------------------------------------------------
#define LPL 10240                 // plane bytes (128 rows x 80B)
#define LSTG (2 * LPL)            // 20480 per stage (A-hi, B-hi)
#define LITE_SMEM (4 * LSTG)      // 81920 -> 2 CTAs/SM

__global__ void __launch_bounds__(256, 2) gemm_lite(
    const __half* __restrict__ Ahi, const __half* __restrict__ Bhi,
    const float* __restrict__ bias, float* __restrict__ Cf,
    int M, int N, int K)
{
    extern __shared__ char smem[];
    const int tid = threadIdx.x;
    const int lane = tid & 31;
    const int warp = tid >> 5;
    const int wm = warp >> 2;
    const int wn = warp & 3;
    const int row0 = blockIdx.y * 128;
    const int col0 = blockIdx.x * 128;

    const int lrow = tid >> 1;
    const int lq = (tid & 1) * 2;

    auto issue = [&](int kc, int s) {
        const uint32_t base = s2u(smem) + s * LSTG;
        const uint32_t sA = base + (uint32_t)lrow * GST + lq * 16;
        const size_t gA = (size_t)(row0 + lrow) * K + kc * 32 + lq * 8;
        cp16(sA, Ahi + gA);
        cp16(sA + 16, Ahi + gA + 8);
        const size_t gB = (size_t)(col0 + lrow) * K + kc * 32 + lq * 8;
        cp16(sA + LPL, Bhi + gB);
        cp16(sA + LPL + 16, Bhi + gB + 8);
    };

    float acc[4][4][4];
#pragma unroll
    for (int i = 0; i < 4; i++)
#pragma unroll
        for (int j = 0; j < 4; j++)
#pragma unroll
            for (int e = 0; e < 4; e++) acc[i][j][e] = 0.f;

    const uint32_t fragoff = (uint32_t)(lane & 15) * GST + (uint32_t)(lane >> 4) * 16;

    const int nch = K / 32;   // 32 -> 32 chunks? K=1024 -> 32. (BK=32)
    // prologue: 3 chunks in flight
    issue(0, 0); CP_COMMIT();
    issue(1, 1); CP_COMMIT();
    issue(2, 2); CP_COMMIT();

    for (int kc = 0; kc < nch; kc++) {
        const int s = kc & 3;
        // retire group kc (3 outstanding normally; tail: wait all)
        if (kc + 2 < nch) { CP_WAIT2(); } else { CP_WAIT0(); }
        __syncthreads();   // all warps done reading buffer (kc-1)%4 (== (kc+3)%4)
        if (kc + 3 < nch) {
            issue(kc + 3, (kc + 3) & 3);
            CP_COMMIT();
        }
        const uint32_t uA = s2u(smem) + s * LSTG;
        const uint32_t uB = uA + LPL;

#pragma unroll
        for (int ks = 0; ks < 2; ks++) {
            const uint32_t kb = (uint32_t)ks * 32;
            uint32_t bh[4][2];
#pragma unroll
            for (int ntp = 0; ntp < 2; ntp++) {
                const uint32_t boff = (uint32_t)(wn * 32 + ntp * 16) * GST + kb + fragoff;
                uint32_t m[4];
                ldmx4(m, uB + boff);
                bh[ntp * 2 + 0][0] = m[0]; bh[ntp * 2 + 1][0] = m[1];
                bh[ntp * 2 + 0][1] = m[2]; bh[ntp * 2 + 1][1] = m[3];
            }
            uint32_t ah[4][4];
#pragma unroll
            for (int mt = 0; mt < 4; mt++) {
                const uint32_t aoff = (uint32_t)(wm * 64 + mt * 16) * GST + kb + fragoff;
                ldmx4(ah[mt], uA + aoff);
            }
#pragma unroll
            for (int mt = 0; mt < 4; mt++)
#pragma unroll
                for (int nt = 0; nt < 4; nt++)
                    mma_f16(acc[mt][nt], ah[mt], bh[nt]);
        }
    }

#pragma unroll
    for (int mt = 0; mt < 4; mt++) {
        const int r = row0 + wm * 64 + mt * 16 + (lane >> 2);
#pragma unroll
        for (int nt = 0; nt < 4; nt++) {
            const int c = col0 + wn * 32 + nt * 8 + (lane & 3) * 2;
            const float bx2 = bias[c];
            const float by2 = bias[c + 1];
            *(float2*)(Cf + (size_t)r * N + c) =
                make_float2(acc[mt][nt][0] + bx2, acc[mt][nt][1] + by2);
            *(float2*)(Cf + (size_t)(r + 8) * N + c) =
                make_float2(acc[mt][nt][2] + bx2, acc[mt][nt][3] + by2);
        }
    }
}

// ---------------------------------------------------------------------------
// Flash attention (unchanged from R15).
// QK: 2-MMA (qh·Khi + qh·Klo). PV: 1-MMA. Output: hi plane only.
// ---------------------------------------------------------------------------
#define AST 144
#define ATL (64 * AST)
#define ASTG (3 * ATL)              // Khi,Klo,Vhi = 27648
#define ATTN_SMEM (2 * ASTG)        // 55296

__global__ void __launch_bounds__(256) flash2(
    const __half* __restrict__ qhi, const __half* __restrict__ qlo,
    __half* __restrict__ ohi)
{
    extern __shared__ char smem[];
    const int tid = threadIdx.x;
    const int lane = tid & 31;
    const int warp = tid >> 5;
    const int qt = blockIdx.x;
    const int bh = blockIdx.y;
    const int b = bh >> 4;
    const int h = bh & 15;

    const uint32_t sb = s2u(smem);
    const uint32_t fragoff = (uint32_t)(lane & 15) * AST + (uint32_t)(lane >> 4) * 16;
    const size_t headoff = (size_t)h * DHd;

    const int krow = tid >> 2;
    const int kcc = (tid & 3) * 2;
    auto issueKV = [&](int kb, int s) {
        const uint32_t sB = sb + s * ASTG + (uint32_t)krow * AST + kcc * 16;
        const size_t g = ((size_t)b * Ss + kb * 64 + krow) * N1 + headoff + kcc * 8;
        cp16(sB,                 qhi + g + Dd);       // K hi
        cp16(sB + 16,            qhi + g + Dd + 8);
        cp16(sB + ATL,           qlo + g + Dd);       // K lo
        cp16(sB + ATL + 16,      qlo + g + Dd + 8);
        cp16(sB + 2 * ATL,       qhi + g + 2 * Dd);   // V hi
        cp16(sB + 2 * ATL + 16,  qhi + g + 2 * Dd + 8);
    };

    issueKV(0, 0);
    CP_COMMIT();
    {
        const int qrow = tid >> 1;
        const int q4 = (tid & 1) * 4;
        const uint32_t sQh = sb + ASTG + (uint32_t)qrow * AST + q4 * 16;
        const size_t g = ((size_t)b * Ss + qt * 128 + qrow) * N1 + headoff + q4 * 8;
#pragma unroll
        for (int i = 0; i < 4; i++)
            cp16(sQh + i * 16, qhi + g + i * 8);
    }
    CP_COMMIT();
    CP_WAIT0();
    __syncthreads();

    uint32_t qh[4][4];
    {
        const uint32_t uQh = sb + ASTG;
#pragma unroll
        for (int j = 0; j < 4; j++) {
            const uint32_t aoff = (uint32_t)(warp * 16) * AST + j * 32 + fragoff;
            ldmx4(qh[j], uQh + aoff);
        }
    }

    float o[8][4];
    float m0 = -1e30f, m1 = -1e30f, l0 = 0.f, l1 = 0.f;
#pragma unroll
    for (int i = 0; i < 8; i++)
#pragma unroll
        for (int e = 0; e < 4; e++) o[i][e] = 0.f;

    for (int kb = 0; kb < Ss / 64; kb++) {
        const int s = kb & 1;
        if (kb > 0) CP_WAIT0();
        __syncthreads();
        if (kb + 1 < Ss / 64) {
            issueKV(kb + 1, s ^ 1);
            CP_COMMIT();
        }
        const uint32_t uKhi = sb + s * ASTG;
        const uint32_t uKlo = uKhi + ATL;
        const uint32_t uVhi = uKhi + 2 * ATL;

        float sc[8][4];
#pragma unroll
        for (int i = 0; i < 8; i++)
#pragma unroll
            for (int e = 0; e < 4; e++) sc[i][e] = 0.f;

#pragma unroll
        for (int j = 0; j < 4; j++) {
#pragma unroll
            for (int g = 0; g < 4; g++) {
                const uint32_t boff = (uint32_t)(g * 16) * AST + j * 32 + fragoff;
                uint32_t mh[4];
                ldmx4(mh, uKhi + boff);
                uint32_t b0[2] = {mh[0], mh[2]}, b1[2] = {mh[1], mh[3]};
                mma_f16(sc[2 * g + 0], qh[j], b0);
                mma_f16(sc[2 * g + 1], qh[j], b1);
            }
#pragma unroll
            for (int g = 0; g < 4; g++) {
                const uint32_t boff = (uint32_t)(g * 16) * AST + j * 32 + fragoff;
                uint32_t ml[4];
                ldmx4(ml, uKlo + boff);
                uint32_t b0[2] = {ml[0], ml[2]}, b1[2] = {ml[1], ml[3]};
                mma_f16(sc[2 * g + 0], qh[j], b0);
                mma_f16(sc[2 * g + 1], qh[j], b1);
            }
        }

        float mx0 = -1e30f, mx1 = -1e30f;
#pragma unroll
        for (int i = 0; i < 8; i++) {
            mx0 = fmaxf(mx0, fmaxf(sc[i][0], sc[i][1]));
            mx1 = fmaxf(mx1, fmaxf(sc[i][2], sc[i][3]));
        }
        mx0 = fmaxf(mx0, __shfl_xor_sync(0xffffffffu, mx0, 1));
        mx0 = fmaxf(mx0, __shfl_xor_sync(0xffffffffu, mx0, 2));
        mx1 = fmaxf(mx1, __shfl_xor_sync(0xffffffffu, mx1, 1));
        mx1 = fmaxf(mx1, __shfl_xor_sync(0xffffffffu, mx1, 2));
        const float mn0 = fmaxf(m0, mx0);
        const float mn1 = fmaxf(m1, mx1);
        const float c0 = __expf(m0 - mn0);
        const float c1 = __expf(m1 - mn1);
        float rs0 = 0.f, rs1 = 0.f;
#pragma unroll
        for (int i = 0; i < 8; i++) {
            sc[i][0] = __expf(sc[i][0] - mn0);
            sc[i][1] = __expf(sc[i][1] - mn0);
            sc[i][2] = __expf(sc[i][2] - mn1);
            sc[i][3] = __expf(sc[i][3] - mn1);
            rs0 += sc[i][0] + sc[i][1];
            rs1 += sc[i][2] + sc[i][3];
        }
        rs0 += __shfl_xor_sync(0xffffffffu, rs0, 1);
        rs0 += __shfl_xor_sync(0xffffffffu, rs0, 2);
        rs1 += __shfl_xor_sync(0xffffffffu, rs1, 1);
        rs1 += __shfl_xor_sync(0xffffffffu, rs1, 2);
        l0 = l0 * c0 + rs0;
        l1 = l1 * c1 + rs1;
        m0 = mn0;
        m1 = mn1;
#pragma unroll
        for (int i = 0; i < 8; i++) {
            o[i][0] *= c0; o[i][1] *= c0;
            o[i][2] *= c1; o[i][3] *= c1;
        }

        uint32_t ph[4][4];
#pragma unroll
        for (int j = 0; j < 4; j++) {
            ph[j][0] = pack_h(sc[2 * j][0],     sc[2 * j][1]);
            ph[j][1] = pack_h(sc[2 * j][2],     sc[2 * j][3]);
            ph[j][2] = pack_h(sc[2 * j + 1][0], sc[2 * j + 1][1]);
            ph[j][3] = pack_h(sc[2 * j + 1][2], sc[2 * j + 1][3]);
        }

#pragma unroll
        for (int j = 0; j < 4; j++) {
#pragma unroll
            for (int g = 0; g < 4; g++) {
                const uint32_t voff = (uint32_t)(j * 16) * AST + g * 32 + fragoff;
                uint32_t mh[4];
                ldmx4t(mh, uVhi + voff);
                uint32_t b0[2] = {mh[0], mh[1]}, b1[2] = {mh[2], mh[3]};
                mma_f16(o[2 * g + 0], ph[j], b0);
                mma_f16(o[2 * g + 1], ph[j], b1);
            }
        }
    }

    const float inv0 = 1.f / l0;
    const float inv1 = 1.f / l1;
    const int r0 = qt * 128 + warp * 16 + (lane >> 2);
    const size_t base0 = ((size_t)b * Ss + r0) * Dd + headoff + (lane & 3) * 2;
    const size_t base1 = base0 + (size_t)8 * Dd;
#pragma unroll
    for (int nt = 0; nt < 8; nt++) {
        ((uint32_t*)ohi)[(base0 + nt * 8) / 2] = pack_h(o[nt][0] * inv0, o[nt][1] * inv0);
        ((uint32_t*)ohi)[(base1 + nt * 8) / 2] = pack_h(o[nt][2] * inv1, o[nt][3] * inv1);
    }
}

// ---------------------------------------------------------------------------
extern "C" void kernel_launch(void* const* d_in, const int* in_sizes, int n_in,
                              void* d_out, int out_size)
{
    (void)in_sizes; (void)n_in; (void)out_size;
    const float* x  = (const float*)d_in[0];
    const float* w1 = (const float*)d_in[1];
    const float* b1 = (const float*)d_in[2];
    const float* w2 = (const float*)d_in[3];
    const float* b2 = (const float*)d_in[4];
    float* out = (float*)d_out;

    __half *xhi, *xlo, *w1hi, *w1lo, *w2hi, *qhi, *qlo, *ahi;
    cudaGetSymbolAddress((void**)&xhi, g_xhi);
    cudaGetSymbolAddress((void**)&xlo, g_xlo);
    cudaGetSymbolAddress((void**)&w1hi, g_w1hi);
    cudaGetSymbolAddress((void**)&w1lo, g_w1lo);
    cudaGetSymbolAddress((void**)&w2hi, g_w2hi);
    cudaGetSymbolAddress((void**)&qhi, g_qkvhi);
    cudaGetSymbolAddress((void**)&qlo, g_qkvlo);
    cudaGetSymbolAddress((void**)&ahi, g_ahi);

    cudaFuncSetAttribute(gemm_hf1, cudaFuncAttributeMaxDynamicSharedMemorySize, GEMM_SMEM);
    cudaFuncSetAttribute(gemm_lite, cudaFuncAttributeMaxDynamicSharedMemorySize, LITE_SMEM);
    cudaFuncSetAttribute(flash2, cudaFuncAttributeMaxDynamicSharedMemorySize, ATTN_SMEM);

    // 0) fused pre-convert
    preconvert<<<NXB + NW1B + NW2B, 256>>>(x, xhi, xlo, w1, w1hi, w1lo, w2, w2hi);

    // 1) QKV projection, heavy-first 1D grid
    gemm_hf1<<<dim3(N1 / 128 * (MM / 128), 1), 256, GEMM_SMEM>>>(
        xhi, xlo, w1hi, w1lo, b1, qhi, qlo, MM, N1, Dd,
        /*n3lim=*/2 * Dd, /*alo=*/0, 2 * Dd, /*wlo=*/Dd, 2 * Dd);
    // 2) attention (QK 2-MMA, PV 1-MMA) -> a hi plane
    flash2<<<dim3(Ss / 128, Bb * Hh), 256, ATTN_SMEM>>>(qhi, qlo, ahi);
    // 3) output projection: lite kernel, 4-stage cp.async ring
    gemm_lite<<<dim3(Dd / 128, MM / 128), 256, LITE_SMEM>>>(
        ahi, w2hi, b2, out, MM, Dd, Dd);
}

// round 17
// speedup vs baseline: 1.3040x; 1.0087x over previous
#include <cuda_runtime.h>
#include <cuda_fp16.h>
#include <cstdint>

// Problem constants
#define Bb 4
#define Ss 2048
#define Dd 1024
#define Hh 16
#define DHd 64
#define MM (Bb * Ss)          // 8192
#define N1 (3 * Dd)           // 3072

// ---------------- global scratch (fp16 hi/lo planes) ----------------
__device__ __half g_xhi[(size_t)MM * Dd];
__device__ __half g_xlo[(size_t)MM * Dd];
__device__ __half g_w1hi[(size_t)N1 * Dd];    // [n][k]
__device__ __half g_w1lo[(size_t)N1 * Dd];
__device__ __half g_w2hi[(size_t)Dd * Dd];    // [n][k]
__device__ __half g_qkvhi[(size_t)MM * N1];
__device__ __half g_qkvlo[(size_t)MM * N1];   // lo valid for K cols only
__device__ __half g_ahi[(size_t)MM * Dd];

// ---------------- helpers ----------------
__device__ __forceinline__ uint32_t s2u(const void* p) {
    uint32_t a;
    asm("{ .reg .u64 t; cvta.to.shared.u64 t, %1; cvt.u32.u64 %0, t; }" : "=r"(a) : "l"(p));
    return a;
}
__device__ __forceinline__ void cp16(uint32_t saddr, const void* gaddr) {
    asm volatile("cp.async.cg.shared.global [%0], [%1], 16;" :: "r"(saddr), "l"(gaddr));
}
#define CP_COMMIT() asm volatile("cp.async.commit_group;" ::: "memory")
#define CP_WAIT0()  asm volatile("cp.async.wait_group 0;" ::: "memory")
#define CP_WAIT2()  asm volatile("cp.async.wait_group 2;" ::: "memory")

__device__ __forceinline__ void ldmx4(uint32_t* r, uint32_t addr) {
    asm volatile("ldmatrix.sync.aligned.m8n8.x4.shared.b16 {%0,%1,%2,%3}, [%4];"
        : "=r"(r[0]), "=r"(r[1]), "=r"(r[2]), "=r"(r[3]) : "r"(addr));
}
__device__ __forceinline__ void ldmx4t(uint32_t* r, uint32_t addr) {
    asm volatile("ldmatrix.sync.aligned.m8n8.x4.trans.shared.b16 {%0,%1,%2,%3}, [%4];"
        : "=r"(r[0]), "=r"(r[1]), "=r"(r[2]), "=r"(r[3]) : "r"(addr));
}
__device__ __forceinline__ void mma_f16(float* c, const uint32_t* a, const uint32_t* b) {
    asm volatile("mma.sync.aligned.m16n8k16.row.col.f32.f16.f16.f32 "
        "{%0,%1,%2,%3}, {%4,%5,%6,%7}, {%8,%9}, {%0,%1,%2,%3};"
        : "+f"(c[0]), "+f"(c[1]), "+f"(c[2]), "+f"(c[3])
        : "r"(a[0]), "r"(a[1]), "r"(a[2]), "r"(a[3]), "r"(b[0]), "r"(b[1]));
}
// fp32 pair -> packed fp16 hi pair + fp16 lo pair (hi = rn(f), lo = rn(f - hi))
__device__ __forceinline__ void cvt_packh(float f0, float f1, uint32_t& hi, uint32_t& lo) {
    __half h0 = __float2half_rn(f0);
    __half h1 = __float2half_rn(f1);
    __half l0 = __float2half_rn(f0 - __half2float(h0));
    __half l1 = __float2half_rn(f1 - __half2float(h1));
    hi = ((uint32_t)__half_as_ushort(h1) << 16) | (uint32_t)__half_as_ushort(h0);
    lo = ((uint32_t)__half_as_ushort(l1) << 16) | (uint32_t)__half_as_ushort(l0);
}
__device__ __forceinline__ uint32_t pack_h(float f0, float f1) {
    __half h0 = __float2half_rn(f0);
    __half h1 = __float2half_rn(f1);
    return ((uint32_t)__half_as_ushort(h1) << 16) | (uint32_t)__half_as_ushort(h0);
}

// ---------------------------------------------------------------------------
// Fused pre-convert (unchanged).
// ---------------------------------------------------------------------------
#define NXB (MM * Dd / 2 / 256)      // 16384
#define NW1B ((N1 / 32) * (Dd / 64)) // 1536
#define NW2B ((Dd / 32) * (Dd / 64)) // 512

__global__ void __launch_bounds__(256) preconvert(
    const float* __restrict__ x, __half* __restrict__ xhi, __half* __restrict__ xlo,
    const float* __restrict__ w1, __half* __restrict__ w1hi, __half* __restrict__ w1lo,
    const float* __restrict__ w2, __half* __restrict__ w2hi)
{
    __shared__ float sm[64][33];
    const int tid = threadIdx.x;
    const int bx = blockIdx.x;

    if (bx < NXB) {
        const int i = bx * 256 + tid;
        float2 v = *(const float2*)(x + 2 * i);
        uint32_t h, l;
        cvt_packh(v.x, v.y, h, l);
        ((uint32_t*)xhi)[i] = h;
        ((uint32_t*)xlo)[i] = l;
        return;
    }

    const float* W;
    __half* Whi;
    __half* Wlo;
    int Nw, n0, k0, write_lo;
    if (bx < NXB + NW1B) {
        const int id = bx - NXB;
        W = w1; Whi = w1hi; Wlo = w1lo; Nw = N1; write_lo = 1;
        n0 = (id % (N1 / 32)) * 32;
        k0 = (id / (N1 / 32)) * 64;
    } else {
        const int id = bx - NXB - NW1B;
        W = w2; Whi = w2hi; Wlo = nullptr; Nw = Dd; write_lo = 0;
        n0 = (id % (Dd / 32)) * 32;
        k0 = (id / (Dd / 32)) * 64;
    }
#pragma unroll
    for (int p = 0; p < 8; p++) {
        const int k = p * 8 + (tid >> 5);
        const int n = tid & 31;
        sm[k][n] = W[(size_t)(k0 + k) * Nw + n0 + n];
    }
    __syncthreads();
#pragma unroll
    for (int p = 0; p < 4; p++) {
        const int n = p * 8 + (tid >> 5);
        const int kp = tid & 31;
        uint32_t h, l;
        cvt_packh(sm[2 * kp][n], sm[2 * kp + 1][n], h, l);
        const size_t idx = ((size_t)(n0 + n) * Dd + k0) / 2 + kp;
        ((uint32_t*)Whi)[idx] = h;
        if (write_lo) ((uint32_t*)Wlo)[idx] = l;
    }
}

// ---------------------------------------------------------------------------
// GEMM1 (unchanged from R16): 128x128 tile, BK=32, 2-stage, heavy-first 1D.
// ---------------------------------------------------------------------------
#define GST 80
#define GTILE (128 * GST)
#define GSTAGE (4 * GTILE)
#define GEMM_SMEM (2 * GSTAGE)

__global__ void __launch_bounds__(256, 2) gemm_hf1(
    const __half* __restrict__ Ahi, const __half* __restrict__ Alo,
    const __half* __restrict__ Bhi, const __half* __restrict__ Blo,
    const float* __restrict__ bias,
    __half* __restrict__ Chi, __half* __restrict__ Clo,
    int M, int N, int K, int n3lim, int alo_lo, int alo_hi,
    int wlo_lo, int wlo_hi)
{
    extern __shared__ char smem[];
    const int tid = threadIdx.x;
    const int lane = tid & 31;
    const int warp = tid >> 5;
    const int wm = warp >> 2;
    const int wn = warp & 3;

    int bx, by;
    {
        const int id = blockIdx.x;
        if (id < 1024) { bx = id & 15; by = id >> 4; }
        else { const int v = id - 1024; bx = 16 + (v & 7); by = v >> 3; }
    }
    const int row0 = by * 128;
    const int col0 = bx * 128;
    const bool use3 = (col0 < n3lim);
    const bool ualo = (col0 >= alo_lo) && (col0 < alo_hi);

    const int lrow = tid >> 1;
    const int lq = (tid & 1) * 2;

    auto issue = [&](int kc, int s) {
        char* stg = smem + s * GSTAGE;
        const uint32_t sA = s2u(stg) + (uint32_t)lrow * GST + lq * 16;
        const size_t gOffA = (size_t)(row0 + lrow) * K + kc * 32 + lq * 8;
        cp16(sA, Ahi + gOffA);
        cp16(sA + 16, Ahi + gOffA + 8);
        if (ualo) {
            cp16(sA + GTILE, Alo + gOffA);
            cp16(sA + GTILE + 16, Alo + gOffA + 8);
        }
        const size_t gOffB = (size_t)(col0 + lrow) * K + kc * 32 + lq * 8;
        cp16(sA + 2 * GTILE, Bhi + gOffB);
        cp16(sA + 2 * GTILE + 16, Bhi + gOffB + 8);
        if (use3) {
            cp16(sA + 3 * GTILE, Blo + gOffB);
            cp16(sA + 3 * GTILE + 16, Blo + gOffB + 8);
        }
    };

    float acc[4][4][4];
#pragma unroll
    for (int i = 0; i < 4; i++)
#pragma unroll
        for (int j = 0; j < 4; j++)
#pragma unroll
            for (int e = 0; e < 4; e++) acc[i][j][e] = 0.f;

    const uint32_t fragoff = (uint32_t)(lane & 15) * GST + (uint32_t)(lane >> 4) * 16;

    issue(0, 0);
    CP_COMMIT();

    const int nch = K / 32;
    for (int kc = 0; kc < nch; kc++) {
        const int s = kc & 1;
        CP_WAIT0();
        __syncthreads();
        if (kc + 1 < nch) {
            issue(kc + 1, s ^ 1);
            CP_COMMIT();
        }
        char* stg = smem + s * GSTAGE;
        const uint32_t uAhi = s2u(stg);
        const uint32_t uAlo = uAhi + GTILE;
        const uint32_t uBhi = uAhi + 2 * GTILE;
        const uint32_t uBlo = uAhi + 3 * GTILE;

#pragma unroll
        for (int ks = 0; ks < 2; ks++) {
            const uint32_t kb = (uint32_t)ks * 32;
            uint32_t bh[4][2], bl[4][2];
#pragma unroll
            for (int ntp = 0; ntp < 2; ntp++) {
                const uint32_t boff = (uint32_t)(wn * 32 + ntp * 16) * GST + kb + fragoff;
                uint32_t m[4];
                ldmx4(m, uBhi + boff);
                bh[ntp * 2 + 0][0] = m[0]; bh[ntp * 2 + 1][0] = m[1];
                bh[ntp * 2 + 0][1] = m[2]; bh[ntp * 2 + 1][1] = m[3];
                if (use3) {
                    ldmx4(m, uBlo + boff);
                    bl[ntp * 2 + 0][0] = m[0]; bl[ntp * 2 + 1][0] = m[1];
                    bl[ntp * 2 + 0][1] = m[2]; bl[ntp * 2 + 1][1] = m[3];
                }
            }
            uint32_t ah[4][4];
#pragma unroll
            for (int mt = 0; mt < 4; mt++) {
                const uint32_t aoff = (uint32_t)(wm * 64 + mt * 16) * GST + kb + fragoff;
                ldmx4(ah[mt], uAhi + aoff);
            }
#pragma unroll
            for (int mt = 0; mt < 4; mt++)
#pragma unroll
                for (int nt = 0; nt < 4; nt++)
                    mma_f16(acc[mt][nt], ah[mt], bh[nt]);
            if (use3) {
#pragma unroll
                for (int mt = 0; mt < 4; mt++)
#pragma unroll
                    for (int nt = 0; nt < 4; nt++)
                        mma_f16(acc[mt][nt], ah[mt], bl[nt]);
            }
            if (ualo) {
#pragma unroll
                for (int mt = 0; mt < 4; mt++) {
                    const uint32_t aoff = (uint32_t)(wm * 64 + mt * 16) * GST + kb + fragoff;
                    uint32_t al[4];
                    ldmx4(al, uAlo + aoff);
#pragma unroll
                    for (int nt = 0; nt < 4; nt++)
                        mma_f16(acc[mt][nt], al, bh[nt]);
                }
            }
        }
    }

    const bool wlo = (col0 >= wlo_lo) && (col0 < wlo_hi);
#pragma unroll
    for (int mt = 0; mt < 4; mt++) {
        const int r = row0 + wm * 64 + mt * 16 + (lane >> 2);
#pragma unroll
        for (int nt = 0; nt < 4; nt++) {
            const int c = col0 + wn * 32 + nt * 8 + (lane & 3) * 2;
            const float bx2 = bias[c];
            const float by2 = bias[c + 1];
            const float f0 = acc[mt][nt][0] + bx2;
            const float f1 = acc[mt][nt][1] + by2;
            const float f2 = acc[mt][nt][2] + bx2;
            const float f3 = acc[mt][nt][3] + by2;
            uint32_t h0, l0, h1, l1;
            cvt_packh(f0, f1, h0, l0);
            cvt_packh(f2, f3, h1, l1);
            const size_t i0 = ((size_t)r * N + c) / 2;
            const size_t i1 = ((size_t)(r + 8) * N + c) / 2;
            ((uint32_t*)Chi)[i0] = h0;
            ((uint32_t*)Chi)[i1] = h1;
            if (wlo) {
                ((uint32_t*)Clo)[i0] = l0;
                ((uint32_t*)Clo)[i1] = l1;
            }
        }
    }
}

// ---------------------------------------------------------------------------
// GEMM2 lite v2: 64x128 tiles (split M -> 1024 CTAs, 3 CTAs/SM, 2.3 waves),
// 4-stage cp.async ring. B (=w2-hi, 2 MB) is L2-resident so doubled B reads
// are cheap. Per-output accumulation order unchanged -> bit-identical.
// ---------------------------------------------------------------------------
#define LPA (64 * GST)            // 5120  A plane (64 rows)
#define LPB (128 * GST)           // 10240 B plane (128 rows)
#define LSTG (LPA + LPB)          // 15360 per stage
#define LITE_SMEM (4 * LSTG)      // 61440 -> 3 CTAs/SM (184320 <= smem cap)

__global__ void __launch_bounds__(256, 3) gemm_lite(
    const __half* __restrict__ Ahi, const __half* __restrict__ Bhi,
    const float* __restrict__ bias, float* __restrict__ Cf,
    int M, int N, int K)
{
    extern __shared__ char smem[];
    const int tid = threadIdx.x;
    const int lane = tid & 31;
    const int warp = tid >> 5;
    const int wm = warp >> 2;        // 0..1 -> 32 rows each
    const int wn = warp & 3;         // 0..3 -> 32 cols each
    const int row0 = blockIdx.y * 64;
    const int col0 = blockIdx.x * 128;

    // A loader: 64 rows x 4 chunks = 256 -> 1 cp16/thread
    const int arow = tid >> 2;
    const int acol = tid & 3;
    // B loader: 128 rows x 4 chunks = 512 -> 2 cp16/thread
    const int brow = tid >> 1;
    const int bq = (tid & 1) * 2;

    auto issue = [&](int kc, int s) {
        const uint32_t base = s2u(smem) + s * LSTG;
        const uint32_t sA = base + (uint32_t)arow * GST + acol * 16;
        const size_t gA = (size_t)(row0 + arow) * K + kc * 32 + acol * 8;
        cp16(sA, Ahi + gA);
        const uint32_t sB = base + LPA + (uint32_t)brow * GST + bq * 16;
        const size_t gB = (size_t)(col0 + brow) * K + kc * 32 + bq * 8;
        cp16(sB, Bhi + gB);
        cp16(sB + 16, Bhi + gB + 8);
    };

    float acc[2][4][4];
#pragma unroll
    for (int i = 0; i < 2; i++)
#pragma unroll
        for (int j = 0; j < 4; j++)
#pragma unroll
            for (int e = 0; e < 4; e++) acc[i][j][e] = 0.f;

    const uint32_t fragoff = (uint32_t)(lane & 15) * GST + (uint32_t)(lane >> 4) * 16;

    const int nch = K / 32;
    issue(0, 0); CP_COMMIT();
    issue(1, 1); CP_COMMIT();
    issue(2, 2); CP_COMMIT();

    for (int kc = 0; kc < nch; kc++) {
        const int s = kc & 3;
        if (kc + 2 < nch) { CP_WAIT2(); } else { CP_WAIT0(); }
        __syncthreads();
        if (kc + 3 < nch) {
            issue(kc + 3, (kc + 3) & 3);
            CP_COMMIT();
        }
        const uint32_t uA = s2u(smem) + s * LSTG;
        const uint32_t uB = uA + LPA;

#pragma unroll
        for (int ks = 0; ks < 2; ks++) {
            const uint32_t kb = (uint32_t)ks * 32;
            uint32_t bh[4][2];
#pragma unroll
            for (int ntp = 0; ntp < 2; ntp++) {
                const uint32_t boff = (uint32_t)(wn * 32 + ntp * 16) * GST + kb + fragoff;
                uint32_t m[4];
                ldmx4(m, uB + boff);
                bh[ntp * 2 + 0][0] = m[0]; bh[ntp * 2 + 1][0] = m[1];
                bh[ntp * 2 + 0][1] = m[2]; bh[ntp * 2 + 1][1] = m[3];
            }
            uint32_t ah[2][4];
#pragma unroll
            for (int mt = 0; mt < 2; mt++) {
                const uint32_t aoff = (uint32_t)(wm * 32 + mt * 16) * GST + kb + fragoff;
                ldmx4(ah[mt], uA + aoff);
            }
#pragma unroll
            for (int mt = 0; mt < 2; mt++)
#pragma unroll
                for (int nt = 0; nt < 4; nt++)
                    mma_f16(acc[mt][nt], ah[mt], bh[nt]);
        }
    }

#pragma unroll
    for (int mt = 0; mt < 2; mt++) {
        const int r = row0 + wm * 32 + mt * 16 + (lane >> 2);
#pragma unroll
        for (int nt = 0; nt < 4; nt++) {
            const int c = col0 + wn * 32 + nt * 8 + (lane & 3) * 2;
            const float bx2 = bias[c];
            const float by2 = bias[c + 1];
            *(float2*)(Cf + (size_t)r * N + c) =
                make_float2(acc[mt][nt][0] + bx2, acc[mt][nt][1] + by2);
            *(float2*)(Cf + (size_t)(r + 8) * N + c) =
                make_float2(acc[mt][nt][2] + bx2, acc[mt][nt][3] + by2);
        }
    }
}

// ---------------------------------------------------------------------------
// Flash attention (unchanged from R16).
// ---------------------------------------------------------------------------
#define AST 144
#define ATL (64 * AST)
#define ASTG (3 * ATL)              // Khi,Klo,Vhi = 27648
#define ATTN_SMEM (2 * ASTG)        // 55296

__global__ void __launch_bounds__(256) flash2(
    const __half* __restrict__ qhi, const __half* __restrict__ qlo,
    __half* __restrict__ ohi)
{
    extern __shared__ char smem[];
    const int tid = threadIdx.x;
    const int lane = tid & 31;
    const int warp = tid >> 5;
    const int qt = blockIdx.x;
    const int bh = blockIdx.y;
    const int b = bh >> 4;
    const int h = bh & 15;

    const uint32_t sb = s2u(smem);
    const uint32_t fragoff = (uint32_t)(lane & 15) * AST + (uint32_t)(lane >> 4) * 16;
    const size_t headoff = (size_t)h * DHd;

    const int krow = tid >> 2;
    const int kcc = (tid & 3) * 2;
    auto issueKV = [&](int kb, int s) {
        const uint32_t sB = sb + s * ASTG + (uint32_t)krow * AST + kcc * 16;
        const size_t g = ((size_t)b * Ss + kb * 64 + krow) * N1 + headoff + kcc * 8;
        cp16(sB,                 qhi + g + Dd);
        cp16(sB + 16,            qhi + g + Dd + 8);
        cp16(sB + ATL,           qlo + g + Dd);
        cp16(sB + ATL + 16,      qlo + g + Dd + 8);
        cp16(sB + 2 * ATL,       qhi + g + 2 * Dd);
        cp16(sB + 2 * ATL + 16,  qhi + g + 2 * Dd + 8);
    };

    issueKV(0, 0);
    CP_COMMIT();
    {
        const int qrow = tid >> 1;
        const int q4 = (tid & 1) * 4;
        const uint32_t sQh = sb + ASTG + (uint32_t)qrow * AST + q4 * 16;
        const size_t g = ((size_t)b * Ss + qt * 128 + qrow) * N1 + headoff + q4 * 8;
#pragma unroll
        for (int i = 0; i < 4; i++)
            cp16(sQh + i * 16, qhi + g + i * 8);
    }
    CP_COMMIT();
    CP_WAIT0();
    __syncthreads();

    uint32_t qh[4][4];
    {
        const uint32_t uQh = sb + ASTG;
#pragma unroll
        for (int j = 0; j < 4; j++) {
            const uint32_t aoff = (uint32_t)(warp * 16) * AST + j * 32 + fragoff;
            ldmx4(qh[j], uQh + aoff);
        }
    }

    float o[8][4];
    float m0 = -1e30f, m1 = -1e30f, l0 = 0.f, l1 = 0.f;
#pragma unroll
    for (int i = 0; i < 8; i++)
#pragma unroll
        for (int e = 0; e < 4; e++) o[i][e] = 0.f;

    for (int kb = 0; kb < Ss / 64; kb++) {
        const int s = kb & 1;
        if (kb > 0) CP_WAIT0();
        __syncthreads();
        if (kb + 1 < Ss / 64) {
            issueKV(kb + 1, s ^ 1);
            CP_COMMIT();
        }
        const uint32_t uKhi = sb + s * ASTG;
        const uint32_t uKlo = uKhi + ATL;
        const uint32_t uVhi = uKhi + 2 * ATL;

        float sc[8][4];
#pragma unroll
        for (int i = 0; i < 8; i++)
#pragma unroll
            for (int e = 0; e < 4; e++) sc[i][e] = 0.f;

#pragma unroll
        for (int j = 0; j < 4; j++) {
#pragma unroll
            for (int g = 0; g < 4; g++) {
                const uint32_t boff = (uint32_t)(g * 16) * AST + j * 32 + fragoff;
                uint32_t mh[4];
                ldmx4(mh, uKhi + boff);
                uint32_t b0[2] = {mh[0], mh[2]}, b1[2] = {mh[1], mh[3]};
                mma_f16(sc[2 * g + 0], qh[j], b0);
                mma_f16(sc[2 * g + 1], qh[j], b1);
            }
#pragma unroll
            for (int g = 0; g < 4; g++) {
                const uint32_t boff = (uint32_t)(g * 16) * AST + j * 32 + fragoff;
                uint32_t ml[4];
                ldmx4(ml, uKlo + boff);
                uint32_t b0[2] = {ml[0], ml[2]}, b1[2] = {ml[1], ml[3]};
                mma_f16(sc[2 * g + 0], qh[j], b0);
                mma_f16(sc[2 * g + 1], qh[j], b1);
            }
        }

        float mx0 = -1e30f, mx1 = -1e30f;
#pragma unroll
        for (int i = 0; i < 8; i++) {
            mx0 = fmaxf(mx0, fmaxf(sc[i][0], sc[i][1]));
            mx1 = fmaxf(mx1, fmaxf(sc[i][2], sc[i][3]));
        }
        mx0 = fmaxf(mx0, __shfl_xor_sync(0xffffffffu, mx0, 1));
        mx0 = fmaxf(mx0, __shfl_xor_sync(0xffffffffu, mx0, 2));
        mx1 = fmaxf(mx1, __shfl_xor_sync(0xffffffffu, mx1, 1));
        mx1 = fmaxf(mx1, __shfl_xor_sync(0xffffffffu, mx1, 2));
        const float mn0 = fmaxf(m0, mx0);
        const float mn1 = fmaxf(m1, mx1);
        const float c0 = __expf(m0 - mn0);
        const float c1 = __expf(m1 - mn1);
        float rs0 = 0.f, rs1 = 0.f;
#pragma unroll
        for (int i = 0; i < 8; i++) {
            sc[i][0] = __expf(sc[i][0] - mn0);
            sc[i][1] = __expf(sc[i][1] - mn0);
            sc[i][2] = __expf(sc[i][2] - mn1);
            sc[i][3] = __expf(sc[i][3] - mn1);
            rs0 += sc[i][0] + sc[i][1];
            rs1 += sc[i][2] + sc[i][3];
        }
        rs0 += __shfl_xor_sync(0xffffffffu, rs0, 1);
        rs0 += __shfl_xor_sync(0xffffffffu, rs0, 2);
        rs1 += __shfl_xor_sync(0xffffffffu, rs1, 1);
        rs1 += __shfl_xor_sync(0xffffffffu, rs1, 2);
        l0 = l0 * c0 + rs0;
        l1 = l1 * c1 + rs1;
        m0 = mn0;
        m1 = mn1;
#pragma unroll
        for (int i = 0; i < 8; i++) {
            o[i][0] *= c0; o[i][1] *= c0;
            o[i][2] *= c1; o[i][3] *= c1;
        }

        uint32_t ph[4][4];
#pragma unroll
        for (int j = 0; j < 4; j++) {
            ph[j][0] = pack_h(sc[2 * j][0],     sc[2 * j][1]);
            ph[j][1] = pack_h(sc[2 * j][2],     sc[2 * j][3]);
            ph[j][2] = pack_h(sc[2 * j + 1][0], sc[2 * j + 1][1]);
            ph[j][3] = pack_h(sc[2 * j + 1][2], sc[2 * j + 1][3]);
        }

#pragma unroll
        for (int j = 0; j < 4; j++) {
#pragma unroll
            for (int g = 0; g < 4; g++) {
                const uint32_t voff = (uint32_t)(j * 16) * AST + g * 32 + fragoff;
                uint32_t mh[4];
                ldmx4t(mh, uVhi + voff);
                uint32_t b0[2] = {mh[0], mh[1]}, b1[2] = {mh[2], mh[3]};
                mma_f16(o[2 * g + 0], ph[j], b0);
                mma_f16(o[2 * g + 1], ph[j], b1);
            }
        }
    }

    const float inv0 = 1.f / l0;
    const float inv1 = 1.f / l1;
    const int r0 = qt * 128 + warp * 16 + (lane >> 2);
    const size_t base0 = ((size_t)b * Ss + r0) * Dd + headoff + (lane & 3) * 2;
    const size_t base1 = base0 + (size_t)8 * Dd;
#pragma unroll
    for (int nt = 0; nt < 8; nt++) {
        ((uint32_t*)ohi)[(base0 + nt * 8) / 2] = pack_h(o[nt][0] * inv0, o[nt][1] * inv0);
        ((uint32_t*)ohi)[(base1 + nt * 8) / 2] = pack_h(o[nt][2] * inv1, o[nt][3] * inv1);
    }
}

// ---------------------------------------------------------------------------
extern "C" void kernel_launch(void* const* d_in, const int* in_sizes, int n_in,
                              void* d_out, int out_size)
{
    (void)in_sizes; (void)n_in; (void)out_size;
    const float* x  = (const float*)d_in[0];
    const float* w1 = (const float*)d_in[1];
    const float* b1 = (const float*)d_in[2];
    const float* w2 = (const float*)d_in[3];
    const float* b2 = (const float*)d_in[4];
    float* out = (float*)d_out;

    __half *xhi, *xlo, *w1hi, *w1lo, *w2hi, *qhi, *qlo, *ahi;
    cudaGetSymbolAddress((void**)&xhi, g_xhi);
    cudaGetSymbolAddress((void**)&xlo, g_xlo);
    cudaGetSymbolAddress((void**)&w1hi, g_w1hi);
    cudaGetSymbolAddress((void**)&w1lo, g_w1lo);
    cudaGetSymbolAddress((void**)&w2hi, g_w2hi);
    cudaGetSymbolAddress((void**)&qhi, g_qkvhi);
    cudaGetSymbolAddress((void**)&qlo, g_qkvlo);
    cudaGetSymbolAddress((void**)&ahi, g_ahi);

    cudaFuncSetAttribute(gemm_hf1, cudaFuncAttributeMaxDynamicSharedMemorySize, GEMM_SMEM);
    cudaFuncSetAttribute(gemm_lite, cudaFuncAttributeMaxDynamicSharedMemorySize, LITE_SMEM);
    cudaFuncSetAttribute(flash2, cudaFuncAttributeMaxDynamicSharedMemorySize, ATTN_SMEM);

    // 0) fused pre-convert
    preconvert<<<NXB + NW1B + NW2B, 256>>>(x, xhi, xlo, w1, w1hi, w1lo, w2, w2hi);

    // 1) QKV projection, heavy-first 1D grid
    gemm_hf1<<<dim3(N1 / 128 * (MM / 128), 1), 256, GEMM_SMEM>>>(
        xhi, xlo, w1hi, w1lo, b1, qhi, qlo, MM, N1, Dd,
        /*n3lim=*/2 * Dd, /*alo=*/0, 2 * Dd, /*wlo=*/Dd, 2 * Dd);
    // 2) attention (QK 2-MMA, PV 1-MMA) -> a hi plane
    flash2<<<dim3(Ss / 128, Bb * Hh), 256, ATTN_SMEM>>>(qhi, qlo, ahi);
    // 3) output projection: 64x128 tiles, 4-stage ring, 3 CTAs/SM
    gemm_lite<<<dim3(Dd / 128, MM / 64), 256, LITE_SMEM>>>(
        ahi, w2hi, b2, out, MM, Dd, Dd);
}